// round 2
// baseline (speedup 1.0000x reference)
#include <cuda_runtime.h>
#include <math.h>
#include <stdint.h>

#define QSCALE 0.08838834764831845f   // (2*64)^-0.5
#define BSCALE 0.7071067811865476f    // 2^-0.5

// ---------------- device scratch ----------------
__device__ float g_q[4*8*512*64];
__device__ float g_k[4*8*512*64];
__device__ float g_v[4*8*512*64];
__device__ float g_bias[4*512*512];
__device__ float g_s1[4*512*768];      // [b*512+s][0:512 ctx | 512:768 E]
__device__ float g_wcomb[512*768];
__device__ float g_bfinal[512];
__device__ float g_M[512*256];
__device__ float g_c[512];

// M[d2][h*32+e] = sum_de W_eo[d2][h*32+de]*W_Ke[de][e];  c[d2] = b_eo[d2]+sum W_eo*b_Ke
__global__ void prep1_kernel(const float* __restrict__ W_Ke, const float* __restrict__ b_Ke,
                             const float* __restrict__ W_eo, const float* __restrict__ b_eo) {
    int d2 = blockIdx.x, j = threadIdx.x;
    int h = j >> 5, e = j & 31;
    const float* weo = W_eo + d2 * 256;
    float acc = 0.f;
    #pragma unroll
    for (int de = 0; de < 32; de++)
        acc = fmaf(weo[h*32 + de], W_Ke[de*32 + e], acc);
    g_M[d2*256 + j] = acc;
    if (j == 0) {
        float c = b_eo[d2];
        for (int jj = 0; jj < 256; jj++) c = fmaf(weo[jj], b_Ke[jj & 31], c);
        g_c[d2] = c;
    }
}

// Wcomb[d][0:512]=W_o[d][0:512]; Wcomb[d][512+j]=sum_d2 W_o[d][512+d2]*M[d2][j]
__global__ void prep2_kernel(const float* __restrict__ W_o, const float* __restrict__ b_o) {
    int d = blockIdx.x, j4 = threadIdx.x;   // 0..63
    const float* wo = W_o + (size_t)d * 1024;
    float4 acc = make_float4(0.f,0.f,0.f,0.f);
    float bacc = 0.f;
    for (int d2 = 0; d2 < 512; d2++) {
        float wv = wo[512 + d2];
        float4 m = *(const float4*)&g_M[d2*256 + j4*4];
        acc.x = fmaf(wv, m.x, acc.x); acc.y = fmaf(wv, m.y, acc.y);
        acc.z = fmaf(wv, m.z, acc.z); acc.w = fmaf(wv, m.w, acc.w);
        if (j4 == 0) bacc = fmaf(wv, g_c[d2], bacc);
    }
    *(float4*)&g_wcomb[(size_t)d*768 + 512 + j4*4] = acc;
    #pragma unroll
    for (int t = 0; t < 8; t++)
        g_wcomb[(size_t)d*768 + j4*8 + t] = wo[j4*8 + t];
    if (j4 == 0) g_bfinal[d] = b_o[d] + bacc;
}

// ---------------- QKV projection: NT tiled SGEMM, scatter to [b][h][s][dk] ----
__global__ void __launch_bounds__(256) proj_kernel(
    const float* __restrict__ Q, const float* __restrict__ K, const float* __restrict__ V,
    const float* __restrict__ WQ, const float* __restrict__ WK, const float* __restrict__ WV,
    const float* __restrict__ bQ, const float* __restrict__ bK, const float* __restrict__ bV) {
    __shared__ float As[16][132];
    __shared__ float Bs[16][68];
    int z = blockIdx.z;
    const float* A    = (z == 0) ? Q  : (z == 1) ? K  : V;
    const float* W    = (z == 0) ? WQ : (z == 1) ? WK : WV;
    const float* bias = (z == 0) ? bQ : (z == 1) ? bK : bV;
    float* dst        = (z == 0) ? g_q : (z == 1) ? g_k : g_v;
    int m0 = blockIdx.y * 128, n0 = blockIdx.x * 64;
    int tid = threadIdx.x, tn = tid & 15, tm = tid >> 4;

    float acc[8][4];
    #pragma unroll
    for (int i = 0; i < 8; i++)
        #pragma unroll
        for (int j = 0; j < 4; j++) acc[i][j] = 0.f;

    for (int k0 = 0; k0 < 512; k0 += 16) {
        #pragma unroll
        for (int r = 0; r < 8; r++) {
            int i = tid + 256*r; int kk = i & 15, m = i >> 4;
            As[kk][m] = A[(size_t)(m0 + m)*512 + k0 + kk];
        }
        #pragma unroll
        for (int r = 0; r < 4; r++) {
            int i = tid + 256*r; int kk = i & 15, n = i >> 4;
            Bs[kk][n] = W[(size_t)(n0 + n)*512 + k0 + kk];
        }
        __syncthreads();
        #pragma unroll
        for (int kk = 0; kk < 16; kk++) {
            float4 a0 = *(const float4*)&As[kk][tm*8];
            float4 a1 = *(const float4*)&As[kk][tm*8 + 4];
            float4 b0 = *(const float4*)&Bs[kk][tn*4];
            float av[8] = {a0.x,a0.y,a0.z,a0.w,a1.x,a1.y,a1.z,a1.w};
            float bv[4] = {b0.x,b0.y,b0.z,b0.w};
            #pragma unroll
            for (int i = 0; i < 8; i++)
                #pragma unroll
                for (int j = 0; j < 4; j++)
                    acc[i][j] = fmaf(av[i], bv[j], acc[i][j]);
        }
        __syncthreads();
    }
    float bv[4];
    #pragma unroll
    for (int j = 0; j < 4; j++) bv[j] = bias[n0 + tn*4 + j];
    float scale = (z == 0) ? QSCALE : 1.0f;
    int np0 = n0 + tn*4, h = np0 >> 6, dk = np0 & 63;
    #pragma unroll
    for (int i = 0; i < 8; i++) {
        int bs = m0 + tm*8 + i;
        int b = bs >> 9, s = bs & 511;
        float4 o;
        o.x = (acc[i][0]+bv[0])*scale; o.y = (acc[i][1]+bv[1])*scale;
        o.z = (acc[i][2]+bv[2])*scale; o.w = (acc[i][3]+bv[3])*scale;
        *(float4*)&dst[(((size_t)(b*8 + h)*512 + s)*64) + dk] = o;
    }
}

// ---------------- edge bias + mask ----------------
__global__ void __launch_bounds__(256) biask_kernel(
    const float* __restrict__ edge, const unsigned char* __restrict__ mask,
    const float* __restrict__ W_eb, const float* __restrict__ b_eb) {
    __shared__ float w[32];
    __shared__ float b0s;
    if (threadIdx.x < 32) w[threadIdx.x] = W_eb[threadIdx.x];
    if (threadIdx.x == 0) b0s = b_eb[0];
    __syncthreads();
    size_t idx = (size_t)blockIdx.x * 256 + threadIdx.x;
    const float4* e4 = (const float4*)(edge + idx * 32);
    float acc = 0.f;
    #pragma unroll
    for (int t = 0; t < 8; t++) {
        float4 ev = e4[t];
        acc = fmaf(ev.x, w[4*t+0], acc);
        acc = fmaf(ev.y, w[4*t+1], acc);
        acc = fmaf(ev.z, w[4*t+2], acc);
        acc = fmaf(ev.w, w[4*t+3], acc);
    }
    float r = (acc + b0s) * BSCALE;
    g_bias[idx] = mask[idx] ? -INFINITY : r;
}

// ---------------- fused attention: grid (64,4), 256 thr, 221184B dyn smem ----
// smem: qs[8*64*8]=4096f | sc[8*512*8]=32768f | stg=18432f
__global__ void __launch_bounds__(256) attn_kernel(const float* __restrict__ edge) {
    extern __shared__ float sm[];
    float* qs  = sm;
    float* sc  = sm + 4096;
    float* stg = sm + 4096 + 32768;
    __shared__ float inv_s[8][8];

    int b = blockIdx.y, n0 = blockIdx.x * 8;
    int tid = threadIdx.x, w = tid >> 5, lane = tid & 31;

    for (int i = tid; i < 4096; i += 256) {
        int kk = i & 63, np = (i >> 6) & 7, h = i >> 9;
        qs[(h*64 + kk)*8 + np] = g_q[(((size_t)(b*8 + h)*512) + n0 + np)*64 + kk];
    }

    // phase A: scores = q.kT + bias
    for (int c = 0; c < 16; c++) {
        __syncthreads();
        for (int i = tid; i < 16384; i += 256) {
            int kk = i & 63, mm = (i >> 6) & 31, h = i >> 11;
            stg[(h*64 + kk)*33 + mm] = g_k[(((size_t)(b*8 + h)*512) + c*32 + mm)*64 + kk];
        }
        __syncthreads();
        int h = w;
        float acc[8];
        #pragma unroll
        for (int i = 0; i < 8; i++) acc[i] = 0.f;
        #pragma unroll 4
        for (int kk = 0; kk < 64; kk++) {
            float kv = stg[(h*64 + kk)*33 + lane];
            float4 q0 = *(const float4*)&qs[(h*64 + kk)*8];
            float4 q1 = *(const float4*)&qs[(h*64 + kk)*8 + 4];
            acc[0]=fmaf(q0.x,kv,acc[0]); acc[1]=fmaf(q0.y,kv,acc[1]);
            acc[2]=fmaf(q0.z,kv,acc[2]); acc[3]=fmaf(q0.w,kv,acc[3]);
            acc[4]=fmaf(q1.x,kv,acc[4]); acc[5]=fmaf(q1.y,kv,acc[5]);
            acc[6]=fmaf(q1.z,kv,acc[6]); acc[7]=fmaf(q1.w,kv,acc[7]);
        }
        int m = c*32 + lane;
        const float* bp = g_bias + ((size_t)b*512 + n0)*512 + m;
        float4 o0, o1;
        o0.x=acc[0]+bp[0];    o0.y=acc[1]+bp[512];
        o0.z=acc[2]+bp[1024]; o0.w=acc[3]+bp[1536];
        o1.x=acc[4]+bp[2048]; o1.y=acc[5]+bp[2560];
        o1.z=acc[6]+bp[3072]; o1.w=acc[7]+bp[3584];
        *(float4*)&sc[(h*512 + m)*8]     = o0;
        *(float4*)&sc[(h*512 + m)*8 + 4] = o1;
    }
    __syncthreads();

    // phase B: softmax (deferred normalization)
    {
        int h = w;
        #pragma unroll
        for (int g = 0; g < 2; g++) {
            float4 mx = make_float4(-INFINITY,-INFINITY,-INFINITY,-INFINITY);
            #pragma unroll 4
            for (int t = 0; t < 16; t++) {
                float4 v = *(const float4*)&sc[(h*512 + t*32 + lane)*8 + g*4];
                mx.x=fmaxf(mx.x,v.x); mx.y=fmaxf(mx.y,v.y);
                mx.z=fmaxf(mx.z,v.z); mx.w=fmaxf(mx.w,v.w);
            }
            #pragma unroll
            for (int off = 16; off > 0; off >>= 1) {
                mx.x=fmaxf(mx.x,__shfl_xor_sync(0xffffffff,mx.x,off));
                mx.y=fmaxf(mx.y,__shfl_xor_sync(0xffffffff,mx.y,off));
                mx.z=fmaxf(mx.z,__shfl_xor_sync(0xffffffff,mx.z,off));
                mx.w=fmaxf(mx.w,__shfl_xor_sync(0xffffffff,mx.w,off));
            }
            float4 sum = make_float4(0.f,0.f,0.f,0.f);
            #pragma unroll 4
            for (int t = 0; t < 16; t++) {
                int m = t*32 + lane;
                float4 v = *(const float4*)&sc[(h*512 + m)*8 + g*4];
                v.x=__expf(v.x-mx.x); v.y=__expf(v.y-mx.y);
                v.z=__expf(v.z-mx.z); v.w=__expf(v.w-mx.w);
                *(float4*)&sc[(h*512 + m)*8 + g*4] = v;
                sum.x+=v.x; sum.y+=v.y; sum.z+=v.z; sum.w+=v.w;
            }
            #pragma unroll
            for (int off = 16; off > 0; off >>= 1) {
                sum.x+=__shfl_xor_sync(0xffffffff,sum.x,off);
                sum.y+=__shfl_xor_sync(0xffffffff,sum.y,off);
                sum.z+=__shfl_xor_sync(0xffffffff,sum.z,off);
                sum.w+=__shfl_xor_sync(0xffffffff,sum.w,off);
            }
            if (lane == 0) {
                inv_s[h][g*4+0]=1.f/sum.x; inv_s[h][g*4+1]=1.f/sum.y;
                inv_s[h][g*4+2]=1.f/sum.z; inv_s[h][g*4+3]=1.f/sum.w;
            }
        }
    }

    // phase C: context + E fused over m-chunks
    float2 ctx[8];
    float  ecc[8];
    #pragma unroll
    for (int i = 0; i < 8; i++) { ctx[i] = make_float2(0.f,0.f); ecc[i] = 0.f; }

    for (int c = 0; c < 16; c++) {
        __syncthreads();
        for (int i = tid; i < 16384; i += 256) {
            int dk = i & 63, mm = (i >> 6) & 31, h = i >> 11;
            stg[(h*32 + mm)*64 + dk] = g_v[(((size_t)(b*8 + h)*512) + c*32 + mm)*64 + dk];
        }
        float* attc = stg + 16384;   // [np*32+mm][h]
        for (int i = tid; i < 2048; i += 256) {
            int h = i & 7, mm = (i >> 3) & 31, np = i >> 8;
            attc[(np*32 + mm)*8 + h] = sc[((h*512) + c*32 + mm)*8 + np];
        }
        __syncthreads();
        {   // context: warp = head
            int h = w;
            #pragma unroll 2
            for (int mm = 0; mm < 32; mm++) {
                float2 vv = *(const float2*)&stg[(h*32 + mm)*64 + lane*2];
                int m = c*32 + mm;
                float4 a0 = *(const float4*)&sc[(h*512 + m)*8];
                float4 a1 = *(const float4*)&sc[(h*512 + m)*8 + 4];
                ctx[0].x=fmaf(a0.x,vv.x,ctx[0].x); ctx[0].y=fmaf(a0.x,vv.y,ctx[0].y);
                ctx[1].x=fmaf(a0.y,vv.x,ctx[1].x); ctx[1].y=fmaf(a0.y,vv.y,ctx[1].y);
                ctx[2].x=fmaf(a0.z,vv.x,ctx[2].x); ctx[2].y=fmaf(a0.z,vv.y,ctx[2].y);
                ctx[3].x=fmaf(a0.w,vv.x,ctx[3].x); ctx[3].y=fmaf(a0.w,vv.y,ctx[3].y);
                ctx[4].x=fmaf(a1.x,vv.x,ctx[4].x); ctx[4].y=fmaf(a1.x,vv.y,ctx[4].y);
                ctx[5].x=fmaf(a1.y,vv.x,ctx[5].x); ctx[5].y=fmaf(a1.y,vv.y,ctx[5].y);
                ctx[6].x=fmaf(a1.z,vv.x,ctx[6].x); ctx[6].y=fmaf(a1.z,vv.y,ctx[6].y);
                ctx[7].x=fmaf(a1.w,vv.x,ctx[7].x); ctx[7].y=fmaf(a1.w,vv.y,ctx[7].y);
            }
        }
        {   // E: warp = n-row (w), lanes = e
            const float* ep = edge + (((size_t)b*512 + n0 + w)*512 + c*32)*32 + lane;
            #pragma unroll 4
            for (int mm = 0; mm < 32; mm++) {
                float ev = __ldg(ep + (size_t)mm*32);
                float4 a0 = *(const float4*)&attc[(w*32 + mm)*8];
                float4 a1 = *(const float4*)&attc[(w*32 + mm)*8 + 4];
                ecc[0]=fmaf(a0.x,ev,ecc[0]); ecc[1]=fmaf(a0.y,ev,ecc[1]);
                ecc[2]=fmaf(a0.z,ev,ecc[2]); ecc[3]=fmaf(a0.w,ev,ecc[3]);
                ecc[4]=fmaf(a1.x,ev,ecc[4]); ecc[5]=fmaf(a1.y,ev,ecc[5]);
                ecc[6]=fmaf(a1.z,ev,ecc[6]); ecc[7]=fmaf(a1.w,ev,ecc[7]);
            }
        }
    }

    {   // write normalized outputs
        int h = w;
        #pragma unroll
        for (int np = 0; np < 8; np++) {
            float is = inv_s[h][np];
            float2 o = make_float2(ctx[np].x*is, ctx[np].y*is);
            *(float2*)&g_s1[((size_t)(b*512) + n0 + np)*768 + h*64 + lane*2] = o;
        }
        #pragma unroll
        for (int h2 = 0; h2 < 8; h2++)
            g_s1[((size_t)(b*512) + n0 + w)*768 + 512 + h2*32 + lane] =
                ecc[h2] * inv_s[h2][w];
    }
}

// ---------------- final GEMM: [ctx|E](2048x768) @ Wcomb^T + bfinal ----------
__global__ void __launch_bounds__(256) final_kernel(float* __restrict__ out) {
    __shared__ float As[16][132];
    __shared__ float Bs[16][68];
    int m0 = blockIdx.y * 128, n0 = blockIdx.x * 64;
    int tid = threadIdx.x, tn = tid & 15, tm = tid >> 4;

    float acc[8][4];
    #pragma unroll
    for (int i = 0; i < 8; i++)
        #pragma unroll
        for (int j = 0; j < 4; j++) acc[i][j] = 0.f;

    for (int k0 = 0; k0 < 768; k0 += 16) {
        #pragma unroll
        for (int r = 0; r < 8; r++) {
            int i = tid + 256*r; int kk = i & 15, m = i >> 4;
            As[kk][m] = g_s1[(size_t)(m0 + m)*768 + k0 + kk];
        }
        #pragma unroll
        for (int r = 0; r < 4; r++) {
            int i = tid + 256*r; int kk = i & 15, n = i >> 4;
            Bs[kk][n] = g_wcomb[(size_t)(n0 + n)*768 + k0 + kk];
        }
        __syncthreads();
        #pragma unroll
        for (int kk = 0; kk < 16; kk++) {
            float4 a0 = *(const float4*)&As[kk][tm*8];
            float4 a1 = *(const float4*)&As[kk][tm*8 + 4];
            float4 b0 = *(const float4*)&Bs[kk][tn*4];
            float av[8] = {a0.x,a0.y,a0.z,a0.w,a1.x,a1.y,a1.z,a1.w};
            float bv[4] = {b0.x,b0.y,b0.z,b0.w};
            #pragma unroll
            for (int i = 0; i < 8; i++)
                #pragma unroll
                for (int j = 0; j < 4; j++)
                    acc[i][j] = fmaf(av[i], bv[j], acc[i][j]);
        }
        __syncthreads();
    }
    float bv[4];
    #pragma unroll
    for (int j = 0; j < 4; j++) bv[j] = g_bfinal[n0 + tn*4 + j];
    #pragma unroll
    for (int i = 0; i < 8; i++) {
        int bs = m0 + tm*8 + i;
        float4 o;
        o.x=acc[i][0]+bv[0]; o.y=acc[i][1]+bv[1];
        o.z=acc[i][2]+bv[2]; o.w=acc[i][3]+bv[3];
        *(float4*)&out[(size_t)bs*512 + n0 + tn*4] = o;
    }
}

extern "C" void kernel_launch(void* const* d_in, const int* in_sizes, int n_in,
                              void* d_out, int out_size) {
    const float* Q    = (const float*)d_in[0];
    const float* K    = (const float*)d_in[1];
    const float* V    = (const float*)d_in[2];
    const unsigned char* mask = (const unsigned char*)d_in[3];
    const float* edge = (const float*)d_in[4];
    const float* W_Q  = (const float*)d_in[5];
    const float* b_Q  = (const float*)d_in[6];
    const float* W_K  = (const float*)d_in[7];
    const float* b_K  = (const float*)d_in[8];
    const float* W_V  = (const float*)d_in[9];
    const float* b_V  = (const float*)d_in[10];
    const float* W_Ke = (const float*)d_in[11];
    const float* b_Ke = (const float*)d_in[12];
    const float* W_eb = (const float*)d_in[13];
    const float* b_eb = (const float*)d_in[14];
    const float* W_eo = (const float*)d_in[15];
    const float* b_eo = (const float*)d_in[16];
    const float* W_o  = (const float*)d_in[17];
    const float* b_o  = (const float*)d_in[18];
    float* out = (float*)d_out;

    static int smem_set = 0;
    if (!smem_set) {
        cudaFuncSetAttribute(attn_kernel, cudaFuncAttributeMaxDynamicSharedMemorySize, 221184);
        smem_set = 1;
    }

    prep1_kernel<<<512, 256>>>(W_Ke, b_Ke, W_eo, b_eo);
    prep2_kernel<<<512, 64>>>(W_o, b_o);
    proj_kernel<<<dim3(8, 16, 3), 256>>>(Q, K, V, W_Q, W_K, W_V, b_Q, b_K, b_V);
    biask_kernel<<<4096, 256>>>(edge, mask, W_eb, b_eb);
    attn_kernel<<<dim3(64, 4), 256, 221184>>>(edge);
    final_kernel<<<dim3(8, 16), 256>>>(out);
}

// round 3
// speedup vs baseline: 1.4844x; 1.4844x over previous
#include <cuda_runtime.h>
#include <math.h>
#include <stdint.h>

#define QSCALE 0.08838834764831845f   // (2*64)^-0.5
#define BSCALE 0.7071067811865476f    // 2^-0.5

// ---------------- device scratch ----------------
__device__ float g_q[4*8*512*64];
__device__ float g_k[4*8*512*64];
__device__ float g_v[4*8*512*64];
__device__ float g_bias[4*512*512];
__device__ float g_p[4*8*512*512];     // normalized attention probs [bh][n][m]
__device__ float g_s1[4*512*768];      // [b*512+s][0:512 ctx | 512:768 E]
__device__ float g_wcomb[512*768];
__device__ float g_bfinal[512];
__device__ float g_M[512*256];
__device__ float g_c[512];

// ---------------- prep: fold W_Ke -> W_eo -> W_o ----------------
__global__ void prep1_kernel(const float* __restrict__ W_Ke, const float* __restrict__ b_Ke,
                             const float* __restrict__ W_eo, const float* __restrict__ b_eo) {
    int d2 = blockIdx.x, j = threadIdx.x;
    int h = j >> 5, e = j & 31;
    const float* weo = W_eo + d2 * 256;
    float acc = 0.f;
    #pragma unroll
    for (int de = 0; de < 32; de++)
        acc = fmaf(weo[h*32 + de], W_Ke[de*32 + e], acc);
    g_M[d2*256 + j] = acc;
    if (j == 0) {
        float c = b_eo[d2];
        for (int jj = 0; jj < 256; jj++) c = fmaf(weo[jj], b_Ke[jj & 31], c);
        g_c[d2] = c;
    }
}

__global__ void prep2_kernel(const float* __restrict__ W_o, const float* __restrict__ b_o) {
    int d = blockIdx.x, j4 = threadIdx.x;   // 0..63
    const float* wo = W_o + (size_t)d * 1024;
    float4 acc = make_float4(0.f,0.f,0.f,0.f);
    float bacc = 0.f;
    for (int d2 = 0; d2 < 512; d2++) {
        float wv = wo[512 + d2];
        float4 m = *(const float4*)&g_M[d2*256 + j4*4];
        acc.x = fmaf(wv, m.x, acc.x); acc.y = fmaf(wv, m.y, acc.y);
        acc.z = fmaf(wv, m.z, acc.z); acc.w = fmaf(wv, m.w, acc.w);
        if (j4 == 0) bacc = fmaf(wv, g_c[d2], bacc);
    }
    *(float4*)&g_wcomb[(size_t)d*768 + 512 + j4*4] = acc;
    #pragma unroll
    for (int t = 0; t < 8; t++)
        g_wcomb[(size_t)d*768 + j4*8 + t] = wo[j4*8 + t];
    if (j4 == 0) g_bfinal[d] = b_o[d] + bacc;
}

// ---------------- QKV projection: 128x128 NT SGEMM, scatter to [b][h][s][dk] ----
__global__ void __launch_bounds__(256) proj_kernel(
    const float* __restrict__ Q, const float* __restrict__ K, const float* __restrict__ V,
    const float* __restrict__ WQ, const float* __restrict__ WK, const float* __restrict__ WV,
    const float* __restrict__ bQ, const float* __restrict__ bK, const float* __restrict__ bV) {
    __shared__ float As[16][132];
    __shared__ float Bs[16][132];
    int z = blockIdx.z;
    const float* A    = (z == 0) ? Q  : (z == 1) ? K  : V;
    const float* W    = (z == 0) ? WQ : (z == 1) ? WK : WV;
    const float* bias = (z == 0) ? bQ : (z == 1) ? bK : bV;
    float* dst        = (z == 0) ? g_q : (z == 1) ? g_k : g_v;
    int m0 = blockIdx.y * 128, n0 = blockIdx.x * 128;
    int tid = threadIdx.x, tn = tid & 15, tm = tid >> 4;

    float acc[8][8];
    #pragma unroll
    for (int i = 0; i < 8; i++)
        #pragma unroll
        for (int j = 0; j < 8; j++) acc[i][j] = 0.f;

    for (int k0 = 0; k0 < 512; k0 += 16) {
        #pragma unroll
        for (int r = 0; r < 8; r++) {
            int i = tid + 256*r; int kk = i & 15, m = i >> 4;
            As[kk][m] = A[(size_t)(m0 + m)*512 + k0 + kk];
            Bs[kk][m] = W[(size_t)(n0 + m)*512 + k0 + kk];
        }
        __syncthreads();
        #pragma unroll
        for (int kk = 0; kk < 16; kk++) {
            float4 a0 = *(const float4*)&As[kk][tm*8];
            float4 a1 = *(const float4*)&As[kk][tm*8 + 4];
            float4 b0 = *(const float4*)&Bs[kk][tn*8];
            float4 b1 = *(const float4*)&Bs[kk][tn*8 + 4];
            float av[8] = {a0.x,a0.y,a0.z,a0.w,a1.x,a1.y,a1.z,a1.w};
            float bv[8] = {b0.x,b0.y,b0.z,b0.w,b1.x,b1.y,b1.z,b1.w};
            #pragma unroll
            for (int i = 0; i < 8; i++)
                #pragma unroll
                for (int j = 0; j < 8; j++)
                    acc[i][j] = fmaf(av[i], bv[j], acc[i][j]);
        }
        __syncthreads();
    }
    float scale = (z == 0) ? QSCALE : 1.0f;
    int np0 = n0 + tn*8;         // 8 output cols, all within one head (8-aligned)
    int h = np0 >> 6, dk = np0 & 63;
    float bb[8];
    #pragma unroll
    for (int j = 0; j < 8; j++) bb[j] = bias[np0 + j];
    #pragma unroll
    for (int i = 0; i < 8; i++) {
        int bs = m0 + tm*8 + i;
        int b = bs >> 9, s = bs & 511;
        float* o = &dst[(((size_t)(b*8 + h)*512 + s)*64) + dk];
        float4 o0, o1;
        o0.x=(acc[i][0]+bb[0])*scale; o0.y=(acc[i][1]+bb[1])*scale;
        o0.z=(acc[i][2]+bb[2])*scale; o0.w=(acc[i][3]+bb[3])*scale;
        o1.x=(acc[i][4]+bb[4])*scale; o1.y=(acc[i][5]+bb[5])*scale;
        o1.z=(acc[i][6]+bb[6])*scale; o1.w=(acc[i][7]+bb[7])*scale;
        *(float4*)o = o0; *(float4*)(o+4) = o1;
    }
}

// ---------------- edge bias + mask (coalesced, shfl-reduce) ----------------
__global__ void __launch_bounds__(256) biask_kernel(
    const float* __restrict__ edge, const unsigned char* __restrict__ mask,
    const float* __restrict__ W_eb, const float* __restrict__ b_eb) {
    __shared__ float w[32];
    __shared__ float b0s;
    if (threadIdx.x < 32) w[threadIdx.x] = W_eb[threadIdx.x];
    if (threadIdx.x == 0) b0s = b_eb[0];
    __syncthreads();
    int warp = threadIdx.x >> 5, lane = threadIdx.x & 31;
    int g = lane >> 3, sub = lane & 7;
    float w0 = w[sub*4], w1 = w[sub*4+1], w2 = w[sub*4+2], w3 = w[sub*4+3];
    size_t base = ((size_t)blockIdx.x * 8 + warp) * 1024;   // pairs per warp
    for (int step = 0; step < 256; step += 4) {
        float part[4];
        #pragma unroll
        for (int u = 0; u < 4; u++) {
            size_t pb = base + (size_t)(step + u) * 4;
            float4 ev = *(const float4*)(edge + (pb + g)*32 + sub*4);
            float t = ev.x*w0;
            t = fmaf(ev.y, w1, t); t = fmaf(ev.z, w2, t); t = fmaf(ev.w, w3, t);
            part[u] = t;
        }
        #pragma unroll
        for (int u = 0; u < 4; u++) {
            float t = part[u];
            t += __shfl_xor_sync(0xffffffff, t, 4);
            t += __shfl_xor_sync(0xffffffff, t, 2);
            t += __shfl_xor_sync(0xffffffff, t, 1);
            if (sub == 0) {
                size_t p = base + (size_t)(step + u)*4 + g;
                float r = (t + b0s) * BSCALE;
                g_bias[p] = mask[p] ? -INFINITY : r;
            }
        }
    }
}

// ---------------- scores: per (b,h) S = q@kT + bias, 128x128 tile K=64 ----
__global__ void __launch_bounds__(256) scores_kernel() {
    __shared__ float Qs[16][132];
    __shared__ float Ks[16][132];
    int bh = blockIdx.z, b = bh >> 3;
    int n0 = blockIdx.y * 128, m0 = blockIdx.x * 128;
    const float* q = g_q + (size_t)bh * 512 * 64;
    const float* k = g_k + (size_t)bh * 512 * 64;
    int tid = threadIdx.x, tn = tid & 15, tm = tid >> 4;

    float acc[8][8];
    #pragma unroll
    for (int i = 0; i < 8; i++)
        #pragma unroll
        for (int j = 0; j < 8; j++) acc[i][j] = 0.f;

    for (int k0 = 0; k0 < 64; k0 += 16) {
        #pragma unroll
        for (int r = 0; r < 8; r++) {
            int i = tid + 256*r; int kk = i & 15, m = i >> 4;
            Qs[kk][m] = q[(size_t)(n0 + m)*64 + k0 + kk];
            Ks[kk][m] = k[(size_t)(m0 + m)*64 + k0 + kk];
        }
        __syncthreads();
        #pragma unroll
        for (int kk = 0; kk < 16; kk++) {
            float4 a0 = *(const float4*)&Qs[kk][tm*8];
            float4 a1 = *(const float4*)&Qs[kk][tm*8 + 4];
            float4 b0 = *(const float4*)&Ks[kk][tn*8];
            float4 b1 = *(const float4*)&Ks[kk][tn*8 + 4];
            float av[8] = {a0.x,a0.y,a0.z,a0.w,a1.x,a1.y,a1.z,a1.w};
            float bv[8] = {b0.x,b0.y,b0.z,b0.w,b1.x,b1.y,b1.z,b1.w};
            #pragma unroll
            for (int i = 0; i < 8; i++)
                #pragma unroll
                for (int j = 0; j < 8; j++)
                    acc[i][j] = fmaf(av[i], bv[j], acc[i][j]);
        }
        __syncthreads();
    }
    #pragma unroll
    for (int i = 0; i < 8; i++) {
        int n = n0 + tm*8 + i, m = m0 + tn*8;
        const float* bp = &g_bias[((size_t)b*512 + n)*512 + m];
        float4 bb0 = *(const float4*)bp;
        float4 bb1 = *(const float4*)(bp + 4);
        float* o = &g_p[((size_t)bh*512 + n)*512 + m];
        float4 o0, o1;
        o0.x=acc[i][0]+bb0.x; o0.y=acc[i][1]+bb0.y; o0.z=acc[i][2]+bb0.z; o0.w=acc[i][3]+bb0.w;
        o1.x=acc[i][4]+bb1.x; o1.y=acc[i][5]+bb1.y; o1.z=acc[i][6]+bb1.z; o1.w=acc[i][7]+bb1.w;
        *(float4*)o = o0; *(float4*)(o+4) = o1;
    }
}

// ---------------- softmax: warp per row, normalize in place ----------------
__global__ void __launch_bounds__(256) softmax_kernel() {
    int row = blockIdx.x * 8 + (threadIdx.x >> 5);
    int lane = threadIdx.x & 31;
    float* p = g_p + (size_t)row * 512;
    float4 v[4];
    #pragma unroll
    for (int t = 0; t < 4; t++) v[t] = *(const float4*)(p + t*128 + lane*4);
    float mx = -INFINITY;
    #pragma unroll
    for (int t = 0; t < 4; t++) {
        mx = fmaxf(mx, fmaxf(fmaxf(v[t].x, v[t].y), fmaxf(v[t].z, v[t].w)));
    }
    #pragma unroll
    for (int off = 16; off > 0; off >>= 1)
        mx = fmaxf(mx, __shfl_xor_sync(0xffffffff, mx, off));
    float sum = 0.f;
    #pragma unroll
    for (int t = 0; t < 4; t++) {
        v[t].x = __expf(v[t].x - mx); v[t].y = __expf(v[t].y - mx);
        v[t].z = __expf(v[t].z - mx); v[t].w = __expf(v[t].w - mx);
        sum += v[t].x + v[t].y + v[t].z + v[t].w;
    }
    #pragma unroll
    for (int off = 16; off > 0; off >>= 1)
        sum += __shfl_xor_sync(0xffffffff, sum, off);
    float inv = 1.f / sum;
    #pragma unroll
    for (int t = 0; t < 4; t++) {
        v[t].x *= inv; v[t].y *= inv; v[t].z *= inv; v[t].w *= inv;
        *(float4*)(p + t*128 + lane*4) = v[t];
    }
}

// ---------------- context: per (b,h) C = P @ V, 128x64 tile K=512 ----------
__global__ void __launch_bounds__(256) ctx_kernel() {
    __shared__ float As[16][132];
    __shared__ float Bs[16][68];
    int bh = blockIdx.y, b = bh >> 3, h = bh & 7;
    int n0 = blockIdx.x * 128;
    const float* p = g_p + (size_t)bh * 512 * 512;
    const float* v = g_v + (size_t)bh * 512 * 64;
    int tid = threadIdx.x, tn = tid & 15, tm = tid >> 4;

    float acc[8][4];
    #pragma unroll
    for (int i = 0; i < 8; i++)
        #pragma unroll
        for (int j = 0; j < 4; j++) acc[i][j] = 0.f;

    for (int k0 = 0; k0 < 512; k0 += 16) {
        #pragma unroll
        for (int r = 0; r < 8; r++) {
            int i = tid + 256*r; int kk = i & 15, n = i >> 4;
            As[kk][n] = p[(size_t)(n0 + n)*512 + k0 + kk];
        }
        #pragma unroll
        for (int r = 0; r < 4; r++) {
            int i = tid + 256*r; int dk = i & 63, kk = i >> 6;
            Bs[kk][dk] = v[(size_t)(k0 + kk)*64 + dk];
        }
        __syncthreads();
        #pragma unroll
        for (int kk = 0; kk < 16; kk++) {
            float4 a0 = *(const float4*)&As[kk][tm*8];
            float4 a1 = *(const float4*)&As[kk][tm*8 + 4];
            float4 b0 = *(const float4*)&Bs[kk][tn*4];
            float av[8] = {a0.x,a0.y,a0.z,a0.w,a1.x,a1.y,a1.z,a1.w};
            float bv[4] = {b0.x,b0.y,b0.z,b0.w};
            #pragma unroll
            for (int i = 0; i < 8; i++)
                #pragma unroll
                for (int j = 0; j < 4; j++)
                    acc[i][j] = fmaf(av[i], bv[j], acc[i][j]);
        }
        __syncthreads();
    }
    #pragma unroll
    for (int i = 0; i < 8; i++) {
        int n = n0 + tm*8 + i;
        float4 o = make_float4(acc[i][0], acc[i][1], acc[i][2], acc[i][3]);
        *(float4*)&g_s1[((size_t)b*512 + n)*768 + h*64 + tn*4] = o;
    }
}

// ---------------- E accumulation: E[b,n,h,e] = sum_m P[bh,n,m]*edge[b,n,m,e] --
__global__ void __launch_bounds__(256) e_kernel(const float* __restrict__ edge) {
    int tid = threadIdx.x;
    int h = tid & 7, np = (tid >> 3) & 15, es = tid >> 7;  // es in {0,1}
    int b = blockIdx.y, n = blockIdx.x * 16 + np;
    const float* pp = g_p + (((size_t)(b*8 + h) * 512) + n) * 512;
    const float* ep = edge + ((size_t)(b*512 + n) * 512) * 32 + es*16;
    float acc[16];
    #pragma unroll
    for (int j = 0; j < 16; j++) acc[j] = 0.f;
    #pragma unroll 2
    for (int m = 0; m < 512; m++) {
        float a = __ldg(pp + m);
        const float* e = ep + (size_t)m * 32;
        float4 e0 = *(const float4*)(e);
        float4 e1 = *(const float4*)(e + 4);
        float4 e2 = *(const float4*)(e + 8);
        float4 e3 = *(const float4*)(e + 12);
        acc[0]=fmaf(a,e0.x,acc[0]);  acc[1]=fmaf(a,e0.y,acc[1]);
        acc[2]=fmaf(a,e0.z,acc[2]);  acc[3]=fmaf(a,e0.w,acc[3]);
        acc[4]=fmaf(a,e1.x,acc[4]);  acc[5]=fmaf(a,e1.y,acc[5]);
        acc[6]=fmaf(a,e1.z,acc[6]);  acc[7]=fmaf(a,e1.w,acc[7]);
        acc[8]=fmaf(a,e2.x,acc[8]);  acc[9]=fmaf(a,e2.y,acc[9]);
        acc[10]=fmaf(a,e2.z,acc[10]); acc[11]=fmaf(a,e2.w,acc[11]);
        acc[12]=fmaf(a,e3.x,acc[12]); acc[13]=fmaf(a,e3.y,acc[13]);
        acc[14]=fmaf(a,e3.z,acc[14]); acc[15]=fmaf(a,e3.w,acc[15]);
    }
    float* o = &g_s1[((size_t)b*512 + n)*768 + 512 + h*32 + es*16];
    #pragma unroll
    for (int t = 0; t < 4; t++)
        *(float4*)(o + t*4) = make_float4(acc[t*4], acc[t*4+1], acc[t*4+2], acc[t*4+3]);
}

// ---------------- final GEMM: [ctx|E](2048x768) @ Wcomb^T + bfinal ----------
__global__ void __launch_bounds__(256) final_kernel(float* __restrict__ out) {
    __shared__ float As[16][132];
    __shared__ float Bs[16][132];
    int m0 = blockIdx.y * 128, n0 = blockIdx.x * 128;
    int tid = threadIdx.x, tn = tid & 15, tm = tid >> 4;

    float acc[8][8];
    #pragma unroll
    for (int i = 0; i < 8; i++)
        #pragma unroll
        for (int j = 0; j < 8; j++) acc[i][j] = 0.f;

    for (int k0 = 0; k0 < 768; k0 += 16) {
        #pragma unroll
        for (int r = 0; r < 8; r++) {
            int i = tid + 256*r; int kk = i & 15, m = i >> 4;
            As[kk][m] = g_s1[(size_t)(m0 + m)*768 + k0 + kk];
            Bs[kk][m] = g_wcomb[(size_t)(n0 + m)*768 + k0 + kk];
        }
        __syncthreads();
        #pragma unroll
        for (int kk = 0; kk < 16; kk++) {
            float4 a0 = *(const float4*)&As[kk][tm*8];
            float4 a1 = *(const float4*)&As[kk][tm*8 + 4];
            float4 b0 = *(const float4*)&Bs[kk][tn*8];
            float4 b1 = *(const float4*)&Bs[kk][tn*8 + 4];
            float av[8] = {a0.x,a0.y,a0.z,a0.w,a1.x,a1.y,a1.z,a1.w};
            float bv[8] = {b0.x,b0.y,b0.z,b0.w,b1.x,b1.y,b1.z,b1.w};
            #pragma unroll
            for (int i = 0; i < 8; i++)
                #pragma unroll
                for (int j = 0; j < 8; j++)
                    acc[i][j] = fmaf(av[i], bv[j], acc[i][j]);
        }
        __syncthreads();
    }
    float bb[8];
    #pragma unroll
    for (int j = 0; j < 8; j++) bb[j] = g_bfinal[n0 + tn*8 + j];
    #pragma unroll
    for (int i = 0; i < 8; i++) {
        int bs = m0 + tm*8 + i;
        float* o = &out[(size_t)bs*512 + n0 + tn*8];
        float4 o0, o1;
        o0.x=acc[i][0]+bb[0]; o0.y=acc[i][1]+bb[1]; o0.z=acc[i][2]+bb[2]; o0.w=acc[i][3]+bb[3];
        o1.x=acc[i][4]+bb[4]; o1.y=acc[i][5]+bb[5]; o1.z=acc[i][6]+bb[6]; o1.w=acc[i][7]+bb[7];
        *(float4*)o = o0; *(float4*)(o+4) = o1;
    }
}

extern "C" void kernel_launch(void* const* d_in, const int* in_sizes, int n_in,
                              void* d_out, int out_size) {
    const float* Q    = (const float*)d_in[0];
    const float* K    = (const float*)d_in[1];
    const float* V    = (const float*)d_in[2];
    const unsigned char* mask = (const unsigned char*)d_in[3];
    const float* edge = (const float*)d_in[4];
    const float* W_Q  = (const float*)d_in[5];
    const float* b_Q  = (const float*)d_in[6];
    const float* W_K  = (const float*)d_in[7];
    const float* b_K  = (const float*)d_in[8];
    const float* W_V  = (const float*)d_in[9];
    const float* b_V  = (const float*)d_in[10];
    const float* W_Ke = (const float*)d_in[11];
    const float* b_Ke = (const float*)d_in[12];
    const float* W_eb = (const float*)d_in[13];
    const float* b_eb = (const float*)d_in[14];
    const float* W_eo = (const float*)d_in[15];
    const float* b_eo = (const float*)d_in[16];
    const float* W_o  = (const float*)d_in[17];
    const float* b_o  = (const float*)d_in[18];
    float* out = (float*)d_out;

    prep1_kernel<<<512, 256>>>(W_Ke, b_Ke, W_eo, b_eo);
    prep2_kernel<<<512, 64>>>(W_o, b_o);
    proj_kernel<<<dim3(4, 16, 3), 256>>>(Q, K, V, W_Q, W_K, W_V, b_Q, b_K, b_V);
    biask_kernel<<<128, 256>>>(edge, mask, W_eb, b_eb);
    scores_kernel<<<dim3(4, 4, 32), 256>>>();
    softmax_kernel<<<2048, 256>>>();
    ctx_kernel<<<dim3(4, 32), 256>>>();
    e_kernel<<<dim3(32, 4), 256>>>(edge);
    final_kernel<<<dim3(4, 16), 256>>>(out);
}

// round 4
// speedup vs baseline: 1.8627x; 1.2548x over previous
#include <cuda_runtime.h>
#include <math.h>
#include <stdint.h>

#define QSCALE 0.08838834764831845f   // (2*64)^-0.5
#define BSCALE 0.7071067811865476f    // 2^-0.5

// ---------------- device scratch ----------------
__device__ float g_q[4*8*512*64];
__device__ float g_k[4*8*512*64];
__device__ float g_v[4*8*512*64];
__device__ float g_bias[4*512*512];
__device__ float g_p[4*8*512*512];     // normalized attention probs [bh][n][m]
__device__ float g_s1[4*512*768];      // [b*512+s][0:512 ctx | 512:768 E]
__device__ float g_wcomb[512*768];
__device__ float g_bfinal[512];
__device__ float g_M[512*256];
__device__ float g_c[512];

// ---------------- cp.async helpers ----------------
__device__ __forceinline__ void cp4(void* s, const void* g) {
    unsigned sa = (unsigned)__cvta_generic_to_shared(s);
    asm volatile("cp.async.ca.shared.global [%0], [%1], 4;" :: "r"(sa), "l"(g));
}
__device__ __forceinline__ void cp_commit() {
    asm volatile("cp.async.commit_group;");
}
__device__ __forceinline__ void cp_wait1() {
    asm volatile("cp.async.wait_group 1;");
}
__device__ __forceinline__ void cp_wait0() {
    asm volatile("cp.async.wait_group 0;");
}

// ---------------- prep: fold W_Ke -> W_eo -> W_o ----------------
__global__ void prep1_kernel(const float* __restrict__ W_Ke, const float* __restrict__ b_Ke,
                             const float* __restrict__ W_eo, const float* __restrict__ b_eo) {
    int d2 = blockIdx.x, j = threadIdx.x;
    int h = j >> 5, e = j & 31;
    const float* weo = W_eo + d2 * 256;
    float acc = 0.f;
    #pragma unroll
    for (int de = 0; de < 32; de++)
        acc = fmaf(weo[h*32 + de], W_Ke[de*32 + e], acc);
    g_M[d2*256 + j] = acc;
    if (j == 0) {
        float c = b_eo[d2];
        for (int jj = 0; jj < 256; jj++) c = fmaf(weo[jj], b_Ke[jj & 31], c);
        g_c[d2] = c;
    }
}

__global__ void prep2_kernel(const float* __restrict__ W_o, const float* __restrict__ b_o) {
    int d = blockIdx.x, j4 = threadIdx.x;   // 0..63
    const float* wo = W_o + (size_t)d * 1024;
    float4 acc = make_float4(0.f,0.f,0.f,0.f);
    float bacc = 0.f;
    for (int d2 = 0; d2 < 512; d2++) {
        float wv = wo[512 + d2];
        float4 m = *(const float4*)&g_M[d2*256 + j4*4];
        acc.x = fmaf(wv, m.x, acc.x); acc.y = fmaf(wv, m.y, acc.y);
        acc.z = fmaf(wv, m.z, acc.z); acc.w = fmaf(wv, m.w, acc.w);
        if (j4 == 0) bacc = fmaf(wv, g_c[d2], bacc);
    }
    *(float4*)&g_wcomb[(size_t)d*768 + 512 + j4*4] = acc;
    #pragma unroll
    for (int t = 0; t < 8; t++)
        g_wcomb[(size_t)d*768 + j4*8 + t] = wo[j4*8 + t];
    if (j4 == 0) g_bfinal[d] = b_o[d] + bacc;
}

// ---------------- QKV projection: 128x128 NT SGEMM (cp.async pipelined) ----
__global__ void __launch_bounds__(256) proj_kernel(
    const float* __restrict__ Q, const float* __restrict__ K, const float* __restrict__ V,
    const float* __restrict__ WQ, const float* __restrict__ WK, const float* __restrict__ WV,
    const float* __restrict__ bQ, const float* __restrict__ bK, const float* __restrict__ bV) {
    __shared__ float As[2][16][132];
    __shared__ float Bs[2][16][132];
    int z = blockIdx.z;
    const float* A    = (z == 0) ? Q  : (z == 1) ? K  : V;
    const float* W    = (z == 0) ? WQ : (z == 1) ? WK : WV;
    const float* bias = (z == 0) ? bQ : (z == 1) ? bK : bV;
    float* dst        = (z == 0) ? g_q : (z == 1) ? g_k : g_v;
    int m0 = blockIdx.y * 128, n0 = blockIdx.x * 128;
    int tid = threadIdx.x, tn = tid & 15, tm = tid >> 4;

    float acc[8][8];
    #pragma unroll
    for (int i = 0; i < 8; i++)
        #pragma unroll
        for (int j = 0; j < 8; j++) acc[i][j] = 0.f;

    // prologue
    #pragma unroll
    for (int r = 0; r < 8; r++) {
        int i = tid + 256*r; int kk = i & 15, m = i >> 4;
        cp4(&As[0][kk][m], &A[(size_t)(m0 + m)*512 + kk]);
        cp4(&Bs[0][kk][m], &W[(size_t)(n0 + m)*512 + kk]);
    }
    cp_commit();

    for (int it = 0; it < 32; it++) {
        if (it < 31) {
            int k0 = (it + 1) * 16, buf = (it + 1) & 1;
            #pragma unroll
            for (int r = 0; r < 8; r++) {
                int i = tid + 256*r; int kk = i & 15, m = i >> 4;
                cp4(&As[buf][kk][m], &A[(size_t)(m0 + m)*512 + k0 + kk]);
                cp4(&Bs[buf][kk][m], &W[(size_t)(n0 + m)*512 + k0 + kk]);
            }
            cp_commit();
            cp_wait1();
        } else cp_wait0();
        __syncthreads();
        int cb = it & 1;
        #pragma unroll
        for (int kk = 0; kk < 16; kk++) {
            float4 a0 = *(const float4*)&As[cb][kk][tm*8];
            float4 a1 = *(const float4*)&As[cb][kk][tm*8 + 4];
            float4 b0 = *(const float4*)&Bs[cb][kk][tn*8];
            float4 b1 = *(const float4*)&Bs[cb][kk][tn*8 + 4];
            float av[8] = {a0.x,a0.y,a0.z,a0.w,a1.x,a1.y,a1.z,a1.w};
            float bv[8] = {b0.x,b0.y,b0.z,b0.w,b1.x,b1.y,b1.z,b1.w};
            #pragma unroll
            for (int i = 0; i < 8; i++)
                #pragma unroll
                for (int j = 0; j < 8; j++)
                    acc[i][j] = fmaf(av[i], bv[j], acc[i][j]);
        }
        __syncthreads();
    }
    float scale = (z == 0) ? QSCALE : 1.0f;
    int np0 = n0 + tn*8;
    int h = np0 >> 6, dk = np0 & 63;
    float bb[8];
    #pragma unroll
    for (int j = 0; j < 8; j++) bb[j] = bias[np0 + j];
    #pragma unroll
    for (int i = 0; i < 8; i++) {
        int bs = m0 + tm*8 + i;
        int b = bs >> 9, s = bs & 511;
        float* o = &dst[(((size_t)(b*8 + h)*512 + s)*64) + dk];
        float4 o0, o1;
        o0.x=(acc[i][0]+bb[0])*scale; o0.y=(acc[i][1]+bb[1])*scale;
        o0.z=(acc[i][2]+bb[2])*scale; o0.w=(acc[i][3]+bb[3])*scale;
        o1.x=(acc[i][4]+bb[4])*scale; o1.y=(acc[i][5]+bb[5])*scale;
        o1.z=(acc[i][6]+bb[6])*scale; o1.w=(acc[i][7]+bb[7])*scale;
        *(float4*)o = o0; *(float4*)(o+4) = o1;
    }
}

// ---------------- edge bias + mask: coalesced AND parallel ----------------
__global__ void __launch_bounds__(256) biask_kernel(
    const float* __restrict__ edge, const unsigned char* __restrict__ mask,
    const float* __restrict__ W_eb, const float* __restrict__ b_eb) {
    __shared__ float w[32];
    __shared__ float b0s;
    if (threadIdx.x < 32) w[threadIdx.x] = W_eb[threadIdx.x];
    if (threadIdx.x == 0) b0s = b_eb[0];
    __syncthreads();
    int warp = threadIdx.x >> 5, lane = threadIdx.x & 31;
    int g = lane >> 3, sub = lane & 7;
    float w0 = w[sub*4], w1 = w[sub*4+1], w2 = w[sub*4+2], w3 = w[sub*4+3];
    size_t base = ((size_t)blockIdx.x * 8 + warp) * 128;   // 128 outputs per warp
    for (int step = 0; step < 32; step++) {
        size_t pb = base + (size_t)step * 4;
        float4 ev = *(const float4*)(edge + (pb + g)*32 + sub*4);
        float t = ev.x*w0;
        t = fmaf(ev.y, w1, t); t = fmaf(ev.z, w2, t); t = fmaf(ev.w, w3, t);
        t += __shfl_xor_sync(0xffffffff, t, 4);
        t += __shfl_xor_sync(0xffffffff, t, 2);
        t += __shfl_xor_sync(0xffffffff, t, 1);
        if (sub == 0) {
            size_t p = pb + g;
            float r = (t + b0s) * BSCALE;
            g_bias[p] = mask[p] ? -INFINITY : r;
        }
    }
}

// ---------------- scores + softmax fused: CTA = 32 rows x full 512 cols ----
// grid (16, 32): (n-tile, bh). acc[4][16]/thread, warp owns 4 rows.
__global__ void __launch_bounds__(256) scores_kernel() {
    __shared__ float Qs[64][33];    // [kk][n]
    __shared__ float Ks[16][520];   // [kk][m] chunk
    int bh = blockIdx.y, b = bh >> 3;
    int n0 = blockIdx.x * 32;
    const float* q = g_q + (size_t)bh * 512 * 64;
    const float* k = g_k + (size_t)bh * 512 * 64;
    int tid = threadIdx.x, w = tid >> 5, lane = tid & 31;

    for (int i = tid; i < 2048; i += 256) {
        int kk = i & 63, n = i >> 6;
        Qs[kk][n] = q[(size_t)(n0 + n)*64 + kk];
    }

    float acc[4][16];
    #pragma unroll
    for (int i = 0; i < 4; i++)
        #pragma unroll
        for (int j = 0; j < 16; j++) acc[i][j] = 0.f;

    for (int c = 0; c < 4; c++) {
        __syncthreads();
        for (int i = tid; i < 2048; i += 256) {
            int kq = i & 3, m = i >> 2;
            float4 v = *(const float4*)&k[(size_t)m*64 + c*16 + kq*4];
            Ks[kq*4+0][m] = v.x; Ks[kq*4+1][m] = v.y;
            Ks[kq*4+2][m] = v.z; Ks[kq*4+3][m] = v.w;
        }
        __syncthreads();
        #pragma unroll
        for (int kk = 0; kk < 16; kk++) {
            float a0 = Qs[c*16+kk][w*4+0];
            float a1 = Qs[c*16+kk][w*4+1];
            float a2 = Qs[c*16+kk][w*4+2];
            float a3 = Qs[c*16+kk][w*4+3];
            #pragma unroll
            for (int j = 0; j < 16; j++) {
                float bb = Ks[kk][j*32 + lane];
                acc[0][j] = fmaf(a0, bb, acc[0][j]);
                acc[1][j] = fmaf(a1, bb, acc[1][j]);
                acc[2][j] = fmaf(a2, bb, acc[2][j]);
                acc[3][j] = fmaf(a3, bb, acc[3][j]);
            }
        }
    }

    // bias + softmax + write normalized P
    #pragma unroll
    for (int i = 0; i < 4; i++) {
        int n = n0 + w*4 + i;
        const float* bp = &g_bias[((size_t)b*512 + n)*512 + lane];
        #pragma unroll
        for (int j = 0; j < 16; j++) acc[i][j] += bp[j*32];
        float mx = -INFINITY;
        #pragma unroll
        for (int j = 0; j < 16; j++) mx = fmaxf(mx, acc[i][j]);
        #pragma unroll
        for (int off = 16; off > 0; off >>= 1)
            mx = fmaxf(mx, __shfl_xor_sync(0xffffffff, mx, off));
        float s = 0.f;
        #pragma unroll
        for (int j = 0; j < 16; j++) {
            acc[i][j] = __expf(acc[i][j] - mx);
            s += acc[i][j];
        }
        #pragma unroll
        for (int off = 16; off > 0; off >>= 1)
            s += __shfl_xor_sync(0xffffffff, s, off);
        float inv = 1.f / s;
        float* pr = &g_p[((size_t)bh*512 + n)*512 + lane];
        #pragma unroll
        for (int j = 0; j < 16; j++) pr[j*32] = acc[i][j] * inv;
    }
}

// ---------------- context: per (b,h) C = P @ V (cp.async pipelined) -------
__global__ void __launch_bounds__(256) ctx_kernel() {
    __shared__ float As[2][16][132];
    __shared__ float Bs[2][16][68];
    int bh = blockIdx.y, b = bh >> 3, h = bh & 7;
    int n0 = blockIdx.x * 128;
    const float* p = g_p + (size_t)bh * 512 * 512;
    const float* v = g_v + (size_t)bh * 512 * 64;
    int tid = threadIdx.x, tn = tid & 15, tm = tid >> 4;

    float acc[8][4];
    #pragma unroll
    for (int i = 0; i < 8; i++)
        #pragma unroll
        for (int j = 0; j < 4; j++) acc[i][j] = 0.f;

    #pragma unroll
    for (int r = 0; r < 8; r++) {
        int i = tid + 256*r; int kk = i & 15, n = i >> 4;
        cp4(&As[0][kk][n], &p[(size_t)(n0 + n)*512 + kk]);
    }
    #pragma unroll
    for (int r = 0; r < 4; r++) {
        int i = tid + 256*r; int dk = i & 63, kk = i >> 6;
        cp4(&Bs[0][kk][dk], &v[(size_t)kk*64 + dk]);
    }
    cp_commit();

    for (int it = 0; it < 32; it++) {
        if (it < 31) {
            int k0 = (it + 1) * 16, buf = (it + 1) & 1;
            #pragma unroll
            for (int r = 0; r < 8; r++) {
                int i = tid + 256*r; int kk = i & 15, n = i >> 4;
                cp4(&As[buf][kk][n], &p[(size_t)(n0 + n)*512 + k0 + kk]);
            }
            #pragma unroll
            for (int r = 0; r < 4; r++) {
                int i = tid + 256*r; int dk = i & 63, kk = i >> 6;
                cp4(&Bs[buf][kk][dk], &v[(size_t)(k0 + kk)*64 + dk]);
            }
            cp_commit();
            cp_wait1();
        } else cp_wait0();
        __syncthreads();
        int cb = it & 1;
        #pragma unroll
        for (int kk = 0; kk < 16; kk++) {
            float4 a0 = *(const float4*)&As[cb][kk][tm*8];
            float4 a1 = *(const float4*)&As[cb][kk][tm*8 + 4];
            float4 b0 = *(const float4*)&Bs[cb][kk][tn*4];
            float av[8] = {a0.x,a0.y,a0.z,a0.w,a1.x,a1.y,a1.z,a1.w};
            float bv[4] = {b0.x,b0.y,b0.z,b0.w};
            #pragma unroll
            for (int i = 0; i < 8; i++)
                #pragma unroll
                for (int j = 0; j < 4; j++)
                    acc[i][j] = fmaf(av[i], bv[j], acc[i][j]);
        }
        __syncthreads();
    }
    #pragma unroll
    for (int i = 0; i < 8; i++) {
        int n = n0 + tm*8 + i;
        float4 o = make_float4(acc[i][0], acc[i][1], acc[i][2], acc[i][3]);
        *(float4*)&g_s1[((size_t)b*512 + n)*768 + h*64 + tn*4] = o;
    }
}

// ---------------- E accumulation with smem-staged P ------------------------
// grid (64, 4): n-tile of 8. thread: h=tid&7, np=(tid>>3)&7, es=tid>>6 (8 e's)
__global__ void __launch_bounds__(256) e_kernel(const float* __restrict__ edge) {
    __shared__ float sP[64*33];    // row = np*8+h, 32 mm cols, stride 33
    int tid = threadIdx.x;
    int h = tid & 7, np = (tid >> 3) & 7, es = tid >> 6;
    int b = blockIdx.y, n0 = blockIdx.x * 8;
    int n = n0 + np;
    int row = np*8 + h;
    const float* ep = edge + ((size_t)(b*512 + n) * 512) * 32 + es*8;
    float acc[8];
    #pragma unroll
    for (int j = 0; j < 8; j++) acc[j] = 0.f;

    for (int c = 0; c < 16; c++) {
        __syncthreads();
        #pragma unroll
        for (int i = 0; i < 2; i++) {
            int idx = tid + 256*i;
            int r = idx >> 3, seg = idx & 7;
            int hh = r & 7, nn = r >> 3;
            float4 v = *(const float4*)&g_p[(((size_t)(b*8 + hh)*512) + n0 + nn)*512 + c*32 + seg*4];
            sP[r*33 + seg*4 + 0] = v.x; sP[r*33 + seg*4 + 1] = v.y;
            sP[r*33 + seg*4 + 2] = v.z; sP[r*33 + seg*4 + 3] = v.w;
        }
        __syncthreads();
        #pragma unroll 4
        for (int mm = 0; mm < 32; mm++) {
            float a = sP[row*33 + mm];
            const float* e = ep + (size_t)(c*32 + mm) * 32;
            float4 e0 = *(const float4*)(e);
            float4 e1 = *(const float4*)(e + 4);
            acc[0]=fmaf(a,e0.x,acc[0]); acc[1]=fmaf(a,e0.y,acc[1]);
            acc[2]=fmaf(a,e0.z,acc[2]); acc[3]=fmaf(a,e0.w,acc[3]);
            acc[4]=fmaf(a,e1.x,acc[4]); acc[5]=fmaf(a,e1.y,acc[5]);
            acc[6]=fmaf(a,e1.z,acc[6]); acc[7]=fmaf(a,e1.w,acc[7]);
        }
    }
    float* o = &g_s1[((size_t)b*512 + n)*768 + 512 + h*32 + es*8];
    *(float4*)o     = make_float4(acc[0], acc[1], acc[2], acc[3]);
    *(float4*)(o+4) = make_float4(acc[4], acc[5], acc[6], acc[7]);
}

// ---------------- final GEMM (cp.async pipelined) --------------------------
__global__ void __launch_bounds__(256) final_kernel(float* __restrict__ out) {
    __shared__ float As[2][16][132];
    __shared__ float Bs[2][16][132];
    int m0 = blockIdx.y * 128, n0 = blockIdx.x * 128;
    int tid = threadIdx.x, tn = tid & 15, tm = tid >> 4;

    float acc[8][8];
    #pragma unroll
    for (int i = 0; i < 8; i++)
        #pragma unroll
        for (int j = 0; j < 8; j++) acc[i][j] = 0.f;

    #pragma unroll
    for (int r = 0; r < 8; r++) {
        int i = tid + 256*r; int kk = i & 15, m = i >> 4;
        cp4(&As[0][kk][m], &g_s1[(size_t)(m0 + m)*768 + kk]);
        cp4(&Bs[0][kk][m], &g_wcomb[(size_t)(n0 + m)*768 + kk]);
    }
    cp_commit();

    for (int it = 0; it < 48; it++) {
        if (it < 47) {
            int k0 = (it + 1) * 16, buf = (it + 1) & 1;
            #pragma unroll
            for (int r = 0; r < 8; r++) {
                int i = tid + 256*r; int kk = i & 15, m = i >> 4;
                cp4(&As[buf][kk][m], &g_s1[(size_t)(m0 + m)*768 + k0 + kk]);
                cp4(&Bs[buf][kk][m], &g_wcomb[(size_t)(n0 + m)*768 + k0 + kk]);
            }
            cp_commit();
            cp_wait1();
        } else cp_wait0();
        __syncthreads();
        int cb = it & 1;
        #pragma unroll
        for (int kk = 0; kk < 16; kk++) {
            float4 a0 = *(const float4*)&As[cb][kk][tm*8];
            float4 a1 = *(const float4*)&As[cb][kk][tm*8 + 4];
            float4 b0 = *(const float4*)&Bs[cb][kk][tn*8];
            float4 b1 = *(const float4*)&Bs[cb][kk][tn*8 + 4];
            float av[8] = {a0.x,a0.y,a0.z,a0.w,a1.x,a1.y,a1.z,a1.w};
            float bv[8] = {b0.x,b0.y,b0.z,b0.w,b1.x,b1.y,b1.z,b1.w};
            #pragma unroll
            for (int i = 0; i < 8; i++)
                #pragma unroll
                for (int j = 0; j < 8; j++)
                    acc[i][j] = fmaf(av[i], bv[j], acc[i][j]);
        }
        __syncthreads();
    }
    float bb[8];
    #pragma unroll
    for (int j = 0; j < 8; j++) bb[j] = g_bfinal[n0 + tn*8 + j];
    #pragma unroll
    for (int i = 0; i < 8; i++) {
        int bs = m0 + tm*8 + i;
        float* o = &out[(size_t)bs*512 + n0 + tn*8];
        float4 o0, o1;
        o0.x=acc[i][0]+bb[0]; o0.y=acc[i][1]+bb[1]; o0.z=acc[i][2]+bb[2]; o0.w=acc[i][3]+bb[3];
        o1.x=acc[i][4]+bb[4]; o1.y=acc[i][5]+bb[5]; o1.z=acc[i][6]+bb[6]; o1.w=acc[i][7]+bb[7];
        *(float4*)o = o0; *(float4*)(o+4) = o1;
    }
}

extern "C" void kernel_launch(void* const* d_in, const int* in_sizes, int n_in,
                              void* d_out, int out_size) {
    const float* Q    = (const float*)d_in[0];
    const float* K    = (const float*)d_in[1];
    const float* V    = (const float*)d_in[2];
    const unsigned char* mask = (const unsigned char*)d_in[3];
    const float* edge = (const float*)d_in[4];
    const float* W_Q  = (const float*)d_in[5];
    const float* b_Q  = (const float*)d_in[6];
    const float* W_K  = (const float*)d_in[7];
    const float* b_K  = (const float*)d_in[8];
    const float* W_V  = (const float*)d_in[9];
    const float* b_V  = (const float*)d_in[10];
    const float* W_Ke = (const float*)d_in[11];
    const float* b_Ke = (const float*)d_in[12];
    const float* W_eb = (const float*)d_in[13];
    const float* b_eb = (const float*)d_in[14];
    const float* W_eo = (const float*)d_in[15];
    const float* b_eo = (const float*)d_in[16];
    const float* W_o  = (const float*)d_in[17];
    const float* b_o  = (const float*)d_in[18];
    float* out = (float*)d_out;

    prep1_kernel<<<512, 256>>>(W_Ke, b_Ke, W_eo, b_eo);
    prep2_kernel<<<512, 64>>>(W_o, b_o);
    proj_kernel<<<dim3(4, 16, 3), 256>>>(Q, K, V, W_Q, W_K, W_V, b_Q, b_K, b_V);
    biask_kernel<<<1024, 256>>>(edge, mask, W_eb, b_eb);
    scores_kernel<<<dim3(16, 32), 256>>>();
    ctx_kernel<<<dim3(4, 32), 256>>>();
    e_kernel<<<dim3(64, 4), 256>>>(edge);
    final_kernel<<<dim3(4, 16), 256>>>(out);
}

// round 5
// speedup vs baseline: 2.1852x; 1.1731x over previous
#include <cuda_runtime.h>
#include <math.h>
#include <stdint.h>

#define QSCALE 0.08838834764831845f   // (2*64)^-0.5
#define BSCALE 0.7071067811865476f    // 2^-0.5

// ---------------- device scratch ----------------
__device__ float g_q[4*8*512*64];
__device__ float g_k[4*8*512*64];
__device__ float g_v[4*8*512*64];
__device__ float g_bias[4*512*512];
__device__ float g_p[4*8*512*512];     // normalized attention probs [bh][n][m]
__device__ float g_s1[4*512*768];      // [b*512+s][0:512 ctx | 512:768 E]
__device__ float g_wcomb[512*768];
__device__ float g_bfinal[512];
__device__ float g_M[512*256];
__device__ float g_c[512];

// ---------------- packed fp32x2 FMA (2x FFMA throughput on sm_103a) --------
__device__ __forceinline__ void ffma2(float2& c, float2 a, float2 b) {
    unsigned long long ca = *reinterpret_cast<const unsigned long long*>(&a);
    unsigned long long cb = *reinterpret_cast<const unsigned long long*>(&b);
    unsigned long long cc = *reinterpret_cast<unsigned long long*>(&c);
    asm("fma.rn.f32x2 %0, %1, %2, %0;" : "+l"(cc) : "l"(ca), "l"(cb));
    *reinterpret_cast<unsigned long long*>(&c) = cc;
}

// ---------------- cp.async helpers ----------------
__device__ __forceinline__ void cp4(void* s, const void* g) {
    unsigned sa = (unsigned)__cvta_generic_to_shared(s);
    asm volatile("cp.async.ca.shared.global [%0], [%1], 4;" :: "r"(sa), "l"(g));
}
__device__ __forceinline__ void cp_commit() { asm volatile("cp.async.commit_group;"); }
__device__ __forceinline__ void cp_wait1()  { asm volatile("cp.async.wait_group 1;"); }
__device__ __forceinline__ void cp_wait0()  { asm volatile("cp.async.wait_group 0;"); }

// ---------------- prep: fold W_Ke -> W_eo -> W_o ----------------
__global__ void prep1_kernel(const float* __restrict__ W_Ke, const float* __restrict__ b_Ke,
                             const float* __restrict__ W_eo, const float* __restrict__ b_eo) {
    int d2 = blockIdx.x, j = threadIdx.x;
    int h = j >> 5, e = j & 31;
    const float* weo = W_eo + d2 * 256;
    float acc = 0.f;
    #pragma unroll
    for (int de = 0; de < 32; de++)
        acc = fmaf(weo[h*32 + de], W_Ke[de*32 + e], acc);
    g_M[d2*256 + j] = acc;
    if (j == 0) {
        float c = b_eo[d2];
        for (int jj = 0; jj < 256; jj++) c = fmaf(weo[jj], b_Ke[jj & 31], c);
        g_c[d2] = c;
    }
}

__global__ void prep2_kernel(const float* __restrict__ W_o, const float* __restrict__ b_o) {
    int d = blockIdx.x, j4 = threadIdx.x;   // 0..63
    const float* wo = W_o + (size_t)d * 1024;
    float4 acc = make_float4(0.f,0.f,0.f,0.f);
    float bacc = 0.f;
    for (int d2 = 0; d2 < 512; d2++) {
        float wv = wo[512 + d2];
        float4 m = *(const float4*)&g_M[d2*256 + j4*4];
        acc.x = fmaf(wv, m.x, acc.x); acc.y = fmaf(wv, m.y, acc.y);
        acc.z = fmaf(wv, m.z, acc.z); acc.w = fmaf(wv, m.w, acc.w);
        if (j4 == 0) bacc = fmaf(wv, g_c[d2], bacc);
    }
    *(float4*)&g_wcomb[(size_t)d*768 + 512 + j4*4] = acc;
    #pragma unroll
    for (int t = 0; t < 8; t++)
        g_wcomb[(size_t)d*768 + j4*8 + t] = wo[j4*8 + t];
    if (j4 == 0) g_bfinal[d] = b_o[d] + bacc;
}

// ---------------- QKV projection: 128x128 NT SGEMM (cp.async + f32x2) ------
__global__ void __launch_bounds__(256) proj_kernel(
    const float* __restrict__ Q, const float* __restrict__ K, const float* __restrict__ V,
    const float* __restrict__ WQ, const float* __restrict__ WK, const float* __restrict__ WV,
    const float* __restrict__ bQ, const float* __restrict__ bK, const float* __restrict__ bV) {
    __shared__ float As[2][16][132];
    __shared__ float Bs[2][16][132];
    int z = blockIdx.z;
    const float* A    = (z == 0) ? Q  : (z == 1) ? K  : V;
    const float* W    = (z == 0) ? WQ : (z == 1) ? WK : WV;
    const float* bias = (z == 0) ? bQ : (z == 1) ? bK : bV;
    float* dst        = (z == 0) ? g_q : (z == 1) ? g_k : g_v;
    int m0 = blockIdx.y * 128, n0 = blockIdx.x * 128;
    int tid = threadIdx.x, tn = tid & 15, tm = tid >> 4;

    float2 acc[8][4];
    #pragma unroll
    for (int i = 0; i < 8; i++)
        #pragma unroll
        for (int j = 0; j < 4; j++) acc[i][j] = make_float2(0.f, 0.f);

    #pragma unroll
    for (int r = 0; r < 8; r++) {
        int i = tid + 256*r; int kk = i & 15, m = i >> 4;
        cp4(&As[0][kk][m], &A[(size_t)(m0 + m)*512 + kk]);
        cp4(&Bs[0][kk][m], &W[(size_t)(n0 + m)*512 + kk]);
    }
    cp_commit();

    for (int it = 0; it < 32; it++) {
        if (it < 31) {
            int k0 = (it + 1) * 16, buf = (it + 1) & 1;
            #pragma unroll
            for (int r = 0; r < 8; r++) {
                int i = tid + 256*r; int kk = i & 15, m = i >> 4;
                cp4(&As[buf][kk][m], &A[(size_t)(m0 + m)*512 + k0 + kk]);
                cp4(&Bs[buf][kk][m], &W[(size_t)(n0 + m)*512 + k0 + kk]);
            }
            cp_commit();
            cp_wait1();
        } else cp_wait0();
        __syncthreads();
        int cb = it & 1;
        #pragma unroll
        for (int kk = 0; kk < 16; kk++) {
            float4 a0 = *(const float4*)&As[cb][kk][tm*8];
            float4 a1 = *(const float4*)&As[cb][kk][tm*8 + 4];
            float4 b0 = *(const float4*)&Bs[cb][kk][tn*8];
            float4 b1 = *(const float4*)&Bs[cb][kk][tn*8 + 4];
            float av[8] = {a0.x,a0.y,a0.z,a0.w,a1.x,a1.y,a1.z,a1.w};
            float2 bp[4] = {make_float2(b0.x,b0.y), make_float2(b0.z,b0.w),
                            make_float2(b1.x,b1.y), make_float2(b1.z,b1.w)};
            #pragma unroll
            for (int i = 0; i < 8; i++) {
                float2 aa = make_float2(av[i], av[i]);
                ffma2(acc[i][0], aa, bp[0]);
                ffma2(acc[i][1], aa, bp[1]);
                ffma2(acc[i][2], aa, bp[2]);
                ffma2(acc[i][3], aa, bp[3]);
            }
        }
        __syncthreads();
    }
    float scale = (z == 0) ? QSCALE : 1.0f;
    int np0 = n0 + tn*8;
    int h = np0 >> 6, dk = np0 & 63;
    float bb[8];
    #pragma unroll
    for (int j = 0; j < 8; j++) bb[j] = bias[np0 + j];
    #pragma unroll
    for (int i = 0; i < 8; i++) {
        int bs = m0 + tm*8 + i;
        int b = bs >> 9, s = bs & 511;
        float* o = &dst[(((size_t)(b*8 + h)*512 + s)*64) + dk];
        float4 o0, o1;
        o0.x=(acc[i][0].x+bb[0])*scale; o0.y=(acc[i][0].y+bb[1])*scale;
        o0.z=(acc[i][1].x+bb[2])*scale; o0.w=(acc[i][1].y+bb[3])*scale;
        o1.x=(acc[i][2].x+bb[4])*scale; o1.y=(acc[i][2].y+bb[5])*scale;
        o1.z=(acc[i][3].x+bb[6])*scale; o1.w=(acc[i][3].y+bb[7])*scale;
        *(float4*)o = o0; *(float4*)(o+4) = o1;
    }
}

// ---------------- edge bias + mask ----------------
__global__ void __launch_bounds__(256) biask_kernel(
    const float* __restrict__ edge, const unsigned char* __restrict__ mask,
    const float* __restrict__ W_eb, const float* __restrict__ b_eb) {
    __shared__ float w[32];
    __shared__ float b0s;
    if (threadIdx.x < 32) w[threadIdx.x] = W_eb[threadIdx.x];
    if (threadIdx.x == 0) b0s = b_eb[0];
    __syncthreads();
    int warp = threadIdx.x >> 5, lane = threadIdx.x & 31;
    int g = lane >> 3, sub = lane & 7;
    float w0 = w[sub*4], w1 = w[sub*4+1], w2 = w[sub*4+2], w3 = w[sub*4+3];
    size_t base = ((size_t)blockIdx.x * 8 + warp) * 64;   // 64 outputs per warp
    for (int step = 0; step < 16; step++) {
        size_t pb = base + (size_t)step * 4;
        float4 ev = *(const float4*)(edge + (pb + g)*32 + sub*4);
        float t = ev.x*w0;
        t = fmaf(ev.y, w1, t); t = fmaf(ev.z, w2, t); t = fmaf(ev.w, w3, t);
        t += __shfl_xor_sync(0xffffffff, t, 4);
        t += __shfl_xor_sync(0xffffffff, t, 2);
        t += __shfl_xor_sync(0xffffffff, t, 1);
        if (sub == 0) {
            size_t p = pb + g;
            float r = (t + b0s) * BSCALE;
            g_bias[p] = mask[p] ? -INFINITY : r;
        }
    }
}

// ---------------- scores + softmax fused (f32x2) ---------------------------
// grid (16, 32): CTA = 32 rows x 512 cols. warp owns 4 rows; acc pairs along m.
__global__ void __launch_bounds__(256) scores_kernel() {
    __shared__ float Qs[64][33];    // [kk][n]
    __shared__ float Ks[16][520];   // [kk][m] chunk
    int bh = blockIdx.y, b = bh >> 3;
    int n0 = blockIdx.x * 32;
    const float* q = g_q + (size_t)bh * 512 * 64;
    const float* k = g_k + (size_t)bh * 512 * 64;
    int tid = threadIdx.x, w = tid >> 5, lane = tid & 31;

    for (int i = tid; i < 2048; i += 256) {
        int kk = i & 63, n = i >> 6;
        Qs[kk][n] = q[(size_t)(n0 + n)*64 + kk];
    }

    float2 acc[4][8];   // [row i][m-pair jp]: .x = col 2jp, .y = col 2jp+1
    #pragma unroll
    for (int i = 0; i < 4; i++)
        #pragma unroll
        for (int j = 0; j < 8; j++) acc[i][j] = make_float2(0.f, 0.f);

    for (int c = 0; c < 4; c++) {
        __syncthreads();
        for (int i = tid; i < 2048; i += 256) {
            int kq = i & 3, m = i >> 2;
            float4 v = *(const float4*)&k[(size_t)m*64 + c*16 + kq*4];
            Ks[kq*4+0][m] = v.x; Ks[kq*4+1][m] = v.y;
            Ks[kq*4+2][m] = v.z; Ks[kq*4+3][m] = v.w;
        }
        __syncthreads();
        #pragma unroll
        for (int kk = 0; kk < 16; kk++) {
            float2 aa[4];
            #pragma unroll
            for (int i = 0; i < 4; i++) {
                float a = Qs[c*16+kk][w*4+i];
                aa[i] = make_float2(a, a);
            }
            #pragma unroll
            for (int jp = 0; jp < 8; jp++) {
                float2 bb = make_float2(Ks[kk][(2*jp)*32 + lane],
                                        Ks[kk][(2*jp+1)*32 + lane]);
                ffma2(acc[0][jp], aa[0], bb);
                ffma2(acc[1][jp], aa[1], bb);
                ffma2(acc[2][jp], aa[2], bb);
                ffma2(acc[3][jp], aa[3], bb);
            }
        }
    }

    // bias + softmax + write normalized P
    #pragma unroll
    for (int i = 0; i < 4; i++) {
        int n = n0 + w*4 + i;
        const float* bp = &g_bias[((size_t)b*512 + n)*512 + lane];
        #pragma unroll
        for (int jp = 0; jp < 8; jp++) {
            acc[i][jp].x += bp[(2*jp)*32];
            acc[i][jp].y += bp[(2*jp+1)*32];
        }
        float mx = -INFINITY;
        #pragma unroll
        for (int jp = 0; jp < 8; jp++)
            mx = fmaxf(mx, fmaxf(acc[i][jp].x, acc[i][jp].y));
        #pragma unroll
        for (int off = 16; off > 0; off >>= 1)
            mx = fmaxf(mx, __shfl_xor_sync(0xffffffff, mx, off));
        float s = 0.f;
        #pragma unroll
        for (int jp = 0; jp < 8; jp++) {
            acc[i][jp].x = __expf(acc[i][jp].x - mx);
            acc[i][jp].y = __expf(acc[i][jp].y - mx);
            s += acc[i][jp].x + acc[i][jp].y;
        }
        #pragma unroll
        for (int off = 16; off > 0; off >>= 1)
            s += __shfl_xor_sync(0xffffffff, s, off);
        float inv = 1.f / s;
        float* pr = &g_p[((size_t)bh*512 + n)*512 + lane];
        #pragma unroll
        for (int jp = 0; jp < 8; jp++) {
            pr[(2*jp)*32]   = acc[i][jp].x * inv;
            pr[(2*jp+1)*32] = acc[i][jp].y * inv;
        }
    }
}

// ---------------- context: per (b,h) C = P @ V (cp.async + f32x2) ---------
__global__ void __launch_bounds__(256) ctx_kernel() {
    __shared__ float As[2][16][132];
    __shared__ float Bs[2][16][68];
    int bh = blockIdx.y, b = bh >> 3, h = bh & 7;
    int n0 = blockIdx.x * 128;
    const float* p = g_p + (size_t)bh * 512 * 512;
    const float* v = g_v + (size_t)bh * 512 * 64;
    int tid = threadIdx.x, tn = tid & 15, tm = tid >> 4;

    float2 acc[8][2];
    #pragma unroll
    for (int i = 0; i < 8; i++) {
        acc[i][0] = make_float2(0.f, 0.f);
        acc[i][1] = make_float2(0.f, 0.f);
    }

    #pragma unroll
    for (int r = 0; r < 8; r++) {
        int i = tid + 256*r; int kk = i & 15, n = i >> 4;
        cp4(&As[0][kk][n], &p[(size_t)(n0 + n)*512 + kk]);
    }
    #pragma unroll
    for (int r = 0; r < 4; r++) {
        int i = tid + 256*r; int dk = i & 63, kk = i >> 6;
        cp4(&Bs[0][kk][dk], &v[(size_t)kk*64 + dk]);
    }
    cp_commit();

    for (int it = 0; it < 32; it++) {
        if (it < 31) {
            int k0 = (it + 1) * 16, buf = (it + 1) & 1;
            #pragma unroll
            for (int r = 0; r < 8; r++) {
                int i = tid + 256*r; int kk = i & 15, n = i >> 4;
                cp4(&As[buf][kk][n], &p[(size_t)(n0 + n)*512 + k0 + kk]);
            }
            #pragma unroll
            for (int r = 0; r < 4; r++) {
                int i = tid + 256*r; int dk = i & 63, kk = i >> 6;
                cp4(&Bs[buf][kk][dk], &v[(size_t)(k0 + kk)*64 + dk]);
            }
            cp_commit();
            cp_wait1();
        } else cp_wait0();
        __syncthreads();
        int cb = it & 1;
        #pragma unroll
        for (int kk = 0; kk < 16; kk++) {
            float4 a0 = *(const float4*)&As[cb][kk][tm*8];
            float4 a1 = *(const float4*)&As[cb][kk][tm*8 + 4];
            float4 b0 = *(const float4*)&Bs[cb][kk][tn*4];
            float av[8] = {a0.x,a0.y,a0.z,a0.w,a1.x,a1.y,a1.z,a1.w};
            float2 bp[2] = {make_float2(b0.x,b0.y), make_float2(b0.z,b0.w)};
            #pragma unroll
            for (int i = 0; i < 8; i++) {
                float2 aa = make_float2(av[i], av[i]);
                ffma2(acc[i][0], aa, bp[0]);
                ffma2(acc[i][1], aa, bp[1]);
            }
        }
        __syncthreads();
    }
    #pragma unroll
    for (int i = 0; i < 8; i++) {
        int n = n0 + tm*8 + i;
        float4 o = make_float4(acc[i][0].x, acc[i][0].y, acc[i][1].x, acc[i][1].y);
        *(float4*)&g_s1[((size_t)b*512 + n)*768 + h*64 + tn*4] = o;
    }
}

// ---------------- E accumulation with smem-staged P (f32x2) ----------------
__global__ void __launch_bounds__(256) e_kernel(const float* __restrict__ edge) {
    __shared__ float sP[64*33];
    int tid = threadIdx.x;
    int h = tid & 7, np = (tid >> 3) & 7, es = tid >> 6;
    int b = blockIdx.y, n0 = blockIdx.x * 8;
    int n = n0 + np;
    int row = np*8 + h;
    const float* ep = edge + ((size_t)(b*512 + n) * 512) * 32 + es*8;
    float2 acc[4];
    #pragma unroll
    for (int j = 0; j < 4; j++) acc[j] = make_float2(0.f, 0.f);

    for (int c = 0; c < 16; c++) {
        __syncthreads();
        #pragma unroll
        for (int i = 0; i < 2; i++) {
            int idx = tid + 256*i;
            int r = idx >> 3, seg = idx & 7;
            int hh = r & 7, nn = r >> 3;
            float4 v = *(const float4*)&g_p[(((size_t)(b*8 + hh)*512) + n0 + nn)*512 + c*32 + seg*4];
            sP[r*33 + seg*4 + 0] = v.x; sP[r*33 + seg*4 + 1] = v.y;
            sP[r*33 + seg*4 + 2] = v.z; sP[r*33 + seg*4 + 3] = v.w;
        }
        __syncthreads();
        #pragma unroll 4
        for (int mm = 0; mm < 32; mm++) {
            float a = sP[row*33 + mm];
            float2 aa = make_float2(a, a);
            const float* e = ep + (size_t)(c*32 + mm) * 32;
            float4 e0 = *(const float4*)(e);
            float4 e1 = *(const float4*)(e + 4);
            ffma2(acc[0], aa, make_float2(e0.x, e0.y));
            ffma2(acc[1], aa, make_float2(e0.z, e0.w));
            ffma2(acc[2], aa, make_float2(e1.x, e1.y));
            ffma2(acc[3], aa, make_float2(e1.z, e1.w));
        }
    }
    float* o = &g_s1[((size_t)b*512 + n)*768 + 512 + h*32 + es*8];
    *(float4*)o     = make_float4(acc[0].x, acc[0].y, acc[1].x, acc[1].y);
    *(float4*)(o+4) = make_float4(acc[2].x, acc[2].y, acc[3].x, acc[3].y);
}

// ---------------- final GEMM: 128x64 tiles (cp.async + f32x2) --------------
__global__ void __launch_bounds__(256) final_kernel(float* __restrict__ out) {
    __shared__ float As[2][16][132];
    __shared__ float Bs[2][16][68];
    int m0 = blockIdx.y * 128, n0 = blockIdx.x * 64;
    int tid = threadIdx.x, tn = tid & 15, tm = tid >> 4;

    float2 acc[8][2];
    #pragma unroll
    for (int i = 0; i < 8; i++) {
        acc[i][0] = make_float2(0.f, 0.f);
        acc[i][1] = make_float2(0.f, 0.f);
    }

    #pragma unroll
    for (int r = 0; r < 8; r++) {
        int i = tid + 256*r; int kk = i & 15, m = i >> 4;
        cp4(&As[0][kk][m], &g_s1[(size_t)(m0 + m)*768 + kk]);
    }
    #pragma unroll
    for (int r = 0; r < 4; r++) {
        int i = tid + 256*r; int kk = i & 15, m = i >> 4;
        cp4(&Bs[0][kk][m], &g_wcomb[(size_t)(n0 + m)*768 + kk]);
    }
    cp_commit();

    for (int it = 0; it < 48; it++) {
        if (it < 47) {
            int k0 = (it + 1) * 16, buf = (it + 1) & 1;
            #pragma unroll
            for (int r = 0; r < 8; r++) {
                int i = tid + 256*r; int kk = i & 15, m = i >> 4;
                cp4(&As[buf][kk][m], &g_s1[(size_t)(m0 + m)*768 + k0 + kk]);
            }
            #pragma unroll
            for (int r = 0; r < 4; r++) {
                int i = tid + 256*r; int kk = i & 15, m = i >> 4;
                cp4(&Bs[buf][kk][m], &g_wcomb[(size_t)(n0 + m)*768 + k0 + kk]);
            }
            cp_commit();
            cp_wait1();
        } else cp_wait0();
        __syncthreads();
        int cb = it & 1;
        #pragma unroll
        for (int kk = 0; kk < 16; kk++) {
            float4 a0 = *(const float4*)&As[cb][kk][tm*8];
            float4 a1 = *(const float4*)&As[cb][kk][tm*8 + 4];
            float4 b0 = *(const float4*)&Bs[cb][kk][tn*4];
            float av[8] = {a0.x,a0.y,a0.z,a0.w,a1.x,a1.y,a1.z,a1.w};
            float2 bp[2] = {make_float2(b0.x,b0.y), make_float2(b0.z,b0.w)};
            #pragma unroll
            for (int i = 0; i < 8; i++) {
                float2 aa = make_float2(av[i], av[i]);
                ffma2(acc[i][0], aa, bp[0]);
                ffma2(acc[i][1], aa, bp[1]);
            }
        }
        __syncthreads();
    }
    float bb[4];
    #pragma unroll
    for (int j = 0; j < 4; j++) bb[j] = g_bfinal[n0 + tn*4 + j];
    #pragma unroll
    for (int i = 0; i < 8; i++) {
        int bs = m0 + tm*8 + i;
        float4 o;
        o.x = acc[i][0].x + bb[0]; o.y = acc[i][0].y + bb[1];
        o.z = acc[i][1].x + bb[2]; o.w = acc[i][1].y + bb[3];
        *(float4*)&out[(size_t)bs*512 + n0 + tn*4] = o;
    }
}

extern "C" void kernel_launch(void* const* d_in, const int* in_sizes, int n_in,
                              void* d_out, int out_size) {
    const float* Q    = (const float*)d_in[0];
    const float* K    = (const float*)d_in[1];
    const float* V    = (const float*)d_in[2];
    const unsigned char* mask = (const unsigned char*)d_in[3];
    const float* edge = (const float*)d_in[4];
    const float* W_Q  = (const float*)d_in[5];
    const float* b_Q  = (const float*)d_in[6];
    const float* W_K  = (const float*)d_in[7];
    const float* b_K  = (const float*)d_in[8];
    const float* W_V  = (const float*)d_in[9];
    const float* b_V  = (const float*)d_in[10];
    const float* W_Ke = (const float*)d_in[11];
    const float* b_Ke = (const float*)d_in[12];
    const float* W_eb = (const float*)d_in[13];
    const float* b_eb = (const float*)d_in[14];
    const float* W_eo = (const float*)d_in[15];
    const float* b_eo = (const float*)d_in[16];
    const float* W_o  = (const float*)d_in[17];
    const float* b_o  = (const float*)d_in[18];
    float* out = (float*)d_out;

    prep1_kernel<<<512, 256>>>(W_Ke, b_Ke, W_eo, b_eo);
    prep2_kernel<<<512, 64>>>(W_o, b_o);
    proj_kernel<<<dim3(4, 16, 3), 256>>>(Q, K, V, W_Q, W_K, W_V, b_Q, b_K, b_V);
    biask_kernel<<<2048, 256>>>(edge, mask, W_eb, b_eb);
    scores_kernel<<<dim3(16, 32), 256>>>();
    ctx_kernel<<<dim3(4, 32), 256>>>();
    e_kernel<<<dim3(64, 4), 256>>>(edge);
    final_kernel<<<dim3(8, 16), 256>>>(out);
}

// round 6
// speedup vs baseline: 2.6626x; 1.2185x over previous
#include <cuda_runtime.h>
#include <math.h>
#include <stdint.h>

#define QSCALE 0.08838834764831845f   // (2*64)^-0.5
#define BSCALE 0.7071067811865476f    // 2^-0.5

// ---------------- device scratch ----------------
__device__ float g_q[4*8*512*64];
__device__ float g_k[4*8*512*64];
__device__ float g_v[4*8*512*64];
__device__ float g_bias[4*512*512];
__device__ float g_p[4*8*512*512];     // normalized attention probs [bh][n][m]
__device__ float g_s1[4*512*768];      // [b*512+s][0:512 ctx | 512:768 E]
__device__ float g_wcomb[512*768];
__device__ float g_bfinal[512];
__device__ float g_M[512*256];
__device__ float g_c[512];

// ---------------- packed fp32x2 FMA ----------------
__device__ __forceinline__ void ffma2(float2& c, float2 a, float2 b) {
    unsigned long long ca = *reinterpret_cast<const unsigned long long*>(&a);
    unsigned long long cb = *reinterpret_cast<const unsigned long long*>(&b);
    unsigned long long cc = *reinterpret_cast<unsigned long long*>(&c);
    asm("fma.rn.f32x2 %0, %1, %2, %0;" : "+l"(cc) : "l"(ca), "l"(cb));
    *reinterpret_cast<unsigned long long*>(&c) = cc;
}

// ---------------- tf32 mma helpers ----------------
__device__ __forceinline__ unsigned f2t(float x) {
    unsigned u; asm("cvt.rna.tf32.f32 %0, %1;" : "=r"(u) : "f"(x)); return u;
}
__device__ __forceinline__ void mma8(float4& d, unsigned a0, unsigned a1, unsigned a2, unsigned a3,
                                     unsigned b0, unsigned b1) {
    asm volatile("mma.sync.aligned.m16n8k8.row.col.f32.tf32.tf32.f32 "
                 "{%0,%1,%2,%3},{%4,%5,%6,%7},{%8,%9},{%0,%1,%2,%3};"
                 : "+f"(d.x), "+f"(d.y), "+f"(d.z), "+f"(d.w)
                 : "r"(a0), "r"(a1), "r"(a2), "r"(a3), "r"(b0), "r"(b1));
}

// ---------------- cp.async helpers ----------------
__device__ __forceinline__ void cp4(void* s, const void* g) {
    unsigned sa = (unsigned)__cvta_generic_to_shared(s);
    asm volatile("cp.async.ca.shared.global [%0], [%1], 4;" :: "r"(sa), "l"(g));
}
__device__ __forceinline__ void cp_commit() { asm volatile("cp.async.commit_group;"); }
__device__ __forceinline__ void cp_wait1()  { asm volatile("cp.async.wait_group 1;"); }
__device__ __forceinline__ void cp_wait0()  { asm volatile("cp.async.wait_group 0;"); }

// 4-plane split layout: element (row m, k) of a 16-k stage lives at
//   plane (k&3), offset m*4 + (k>>2).  Plane stride PL (floats), PL/4 = 2 mod 8
// -> fragment float4 LDS are bank-conflict-free, cp.async STS conflict-free.
#define PLA 520   // 128-row planes
#define PLB 264   // 64-row planes

// ---------------- prep: fold W_Ke -> W_eo -> W_o ----------------
__global__ void prep1_kernel(const float* __restrict__ W_Ke, const float* __restrict__ b_Ke,
                             const float* __restrict__ W_eo, const float* __restrict__ b_eo) {
    int d2 = blockIdx.x, j = threadIdx.x;
    int h = j >> 5, e = j & 31;
    const float* weo = W_eo + d2 * 256;
    float acc = 0.f;
    #pragma unroll
    for (int de = 0; de < 32; de++)
        acc = fmaf(weo[h*32 + de], W_Ke[de*32 + e], acc);
    g_M[d2*256 + j] = acc;
    if (j == 0) {
        float c = b_eo[d2];
        for (int jj = 0; jj < 256; jj++) c = fmaf(weo[jj], b_Ke[jj & 31], c);
        g_c[d2] = c;
    }
}

__global__ void prep2_kernel(const float* __restrict__ W_o, const float* __restrict__ b_o) {
    int d = blockIdx.x, j4 = threadIdx.x;   // 0..63
    const float* wo = W_o + (size_t)d * 1024;
    float4 acc = make_float4(0.f,0.f,0.f,0.f);
    float bacc = 0.f;
    for (int d2 = 0; d2 < 512; d2++) {
        float wv = wo[512 + d2];
        float4 m = *(const float4*)&g_M[d2*256 + j4*4];
        acc.x = fmaf(wv, m.x, acc.x); acc.y = fmaf(wv, m.y, acc.y);
        acc.z = fmaf(wv, m.z, acc.z); acc.w = fmaf(wv, m.w, acc.w);
        if (j4 == 0) bacc = fmaf(wv, g_c[d2], bacc);
    }
    *(float4*)&g_wcomb[(size_t)d*768 + 512 + j4*4] = acc;
    #pragma unroll
    for (int t = 0; t < 8; t++)
        g_wcomb[(size_t)d*768 + j4*8 + t] = wo[j4*8 + t];
    if (j4 == 0) g_bfinal[d] = b_o[d] + bacc;
}

// ---------------- QKV projection: tf32 MMA, CTA 128x128 --------------------
__global__ void __launch_bounds__(256) proj_kernel(
    const float* __restrict__ Q, const float* __restrict__ K, const float* __restrict__ V,
    const float* __restrict__ WQ, const float* __restrict__ WK, const float* __restrict__ WV,
    const float* __restrict__ bQ, const float* __restrict__ bK, const float* __restrict__ bV) {
    __shared__ float As[2][4*PLA];
    __shared__ float Bs[2][4*PLA];
    int z = blockIdx.z;
    const float* A    = (z == 0) ? Q  : (z == 1) ? K  : V;
    const float* W    = (z == 0) ? WQ : (z == 1) ? WK : WV;
    const float* bias = (z == 0) ? bQ : (z == 1) ? bK : bV;
    float* dst        = (z == 0) ? g_q : (z == 1) ? g_k : g_v;
    int m0 = blockIdx.y * 128, n0 = blockIdx.x * 128;
    int tid = threadIdx.x, lane = tid & 31, w = tid >> 5;
    int warp_m = (w & 1) * 64, warp_n = (w >> 1) * 32;
    int r = lane >> 2, c = lane & 3;

    float4 acc[4][4];
    #pragma unroll
    for (int i = 0; i < 4; i++)
        #pragma unroll
        for (int j = 0; j < 4; j++) acc[i][j] = make_float4(0.f,0.f,0.f,0.f);

    #pragma unroll
    for (int t = 0; t < 8; t++) {
        int i = tid + 256*t; int kk = i & 15, m = i >> 4;
        int off = (kk & 3)*PLA + m*4 + (kk >> 2);
        cp4(&As[0][off], &A[(size_t)(m0 + m)*512 + kk]);
        cp4(&Bs[0][off], &W[(size_t)(n0 + m)*512 + kk]);
    }
    cp_commit();

    for (int it = 0; it < 32; it++) {
        if (it < 31) {
            int k0 = (it + 1) * 16, buf = (it + 1) & 1;
            #pragma unroll
            for (int t = 0; t < 8; t++) {
                int i = tid + 256*t; int kk = i & 15, m = i >> 4;
                int off = (kk & 3)*PLA + m*4 + (kk >> 2);
                cp4(&As[buf][off], &A[(size_t)(m0 + m)*512 + k0 + kk]);
                cp4(&Bs[buf][off], &W[(size_t)(n0 + m)*512 + k0 + kk]);
            }
            cp_commit();
            cp_wait1();
        } else cp_wait0();
        __syncthreads();
        const float* a = As[it & 1];
        const float* bsm = Bs[it & 1];
        unsigned bu[4][4];
        #pragma unroll
        for (int j = 0; j < 4; j++) {
            float4 v = *(const float4*)&bsm[c*PLA + (warp_n + j*8 + r)*4];
            bu[j][0]=f2t(v.x); bu[j][1]=f2t(v.y); bu[j][2]=f2t(v.z); bu[j][3]=f2t(v.w);
        }
        #pragma unroll
        for (int i = 0; i < 4; i++) {
            float4 lo = *(const float4*)&a[c*PLA + (warp_m + i*16 + r)*4];
            float4 hi = *(const float4*)&a[c*PLA + (warp_m + i*16 + r + 8)*4];
            unsigned a00=f2t(lo.x), a01=f2t(lo.y), a02=f2t(lo.z), a03=f2t(lo.w);
            unsigned a10=f2t(hi.x), a11=f2t(hi.y), a12=f2t(hi.z), a13=f2t(hi.w);
            #pragma unroll
            for (int j = 0; j < 4; j++) {
                mma8(acc[i][j], a00, a10, a01, a11, bu[j][0], bu[j][1]);
                mma8(acc[i][j], a02, a12, a03, a13, bu[j][2], bu[j][3]);
            }
        }
        __syncthreads();
    }
    float scale = (z == 0) ? QSCALE : 1.0f;
    #pragma unroll
    for (int j = 0; j < 4; j++) {
        int np0 = n0 + warp_n + j*8 + 2*c;
        int h = np0 >> 6, dk = np0 & 63;
        float b0v = bias[np0], b1v = bias[np0 + 1];
        #pragma unroll
        for (int i = 0; i < 4; i++) {
            float4 d = acc[i][j];
            int R0 = m0 + warp_m + i*16 + r;
            int R1 = R0 + 8;
            float2 o0 = make_float2((d.x + b0v)*scale, (d.y + b1v)*scale);
            float2 o1 = make_float2((d.z + b0v)*scale, (d.w + b1v)*scale);
            *(float2*)&dst[(((size_t)((R0 >> 9)*8 + h)*512 + (R0 & 511))*64) + dk] = o0;
            *(float2*)&dst[(((size_t)((R1 >> 9)*8 + h)*512 + (R1 & 511))*64) + dk] = o1;
        }
    }
}

// ---------------- edge bias + mask ----------------
__global__ void __launch_bounds__(256) biask_kernel(
    const float* __restrict__ edge, const unsigned char* __restrict__ mask,
    const float* __restrict__ W_eb, const float* __restrict__ b_eb) {
    __shared__ float w[32];
    __shared__ float b0s;
    if (threadIdx.x < 32) w[threadIdx.x] = W_eb[threadIdx.x];
    if (threadIdx.x == 0) b0s = b_eb[0];
    __syncthreads();
    int warp = threadIdx.x >> 5, lane = threadIdx.x & 31;
    int g = lane >> 3, sub = lane & 7;
    float w0 = w[sub*4], w1 = w[sub*4+1], w2 = w[sub*4+2], w3 = w[sub*4+3];
    size_t base = ((size_t)blockIdx.x * 8 + warp) * 64;
    for (int step = 0; step < 16; step++) {
        size_t pb = base + (size_t)step * 4;
        float4 ev = *(const float4*)(edge + (pb + g)*32 + sub*4);
        float t = ev.x*w0;
        t = fmaf(ev.y, w1, t); t = fmaf(ev.z, w2, t); t = fmaf(ev.w, w3, t);
        t += __shfl_xor_sync(0xffffffff, t, 4);
        t += __shfl_xor_sync(0xffffffff, t, 2);
        t += __shfl_xor_sync(0xffffffff, t, 1);
        if (sub == 0) {
            size_t p = pb + g;
            float r = (t + b0s) * BSCALE;
            g_bias[p] = mask[p] ? -INFINITY : r;
        }
    }
}

// ---------------- scores + softmax fused (fp32 scalar, f32x2) --------------
__global__ void __launch_bounds__(256) scores_kernel() {
    __shared__ float Qs[64][33];
    __shared__ float Ks[16][520];
    int bh = blockIdx.y, b = bh >> 3;
    int n0 = blockIdx.x * 32;
    const float* q = g_q + (size_t)bh * 512 * 64;
    const float* k = g_k + (size_t)bh * 512 * 64;
    int tid = threadIdx.x, w = tid >> 5, lane = tid & 31;

    for (int i = tid; i < 2048; i += 256) {
        int kk = i & 63, n = i >> 6;
        Qs[kk][n] = q[(size_t)(n0 + n)*64 + kk];
    }
    float2 acc[4][8];
    #pragma unroll
    for (int i = 0; i < 4; i++)
        #pragma unroll
        for (int j = 0; j < 8; j++) acc[i][j] = make_float2(0.f, 0.f);

    for (int c = 0; c < 4; c++) {
        __syncthreads();
        for (int i = tid; i < 2048; i += 256) {
            int kq = i & 3, m = i >> 2;
            float4 v = *(const float4*)&k[(size_t)m*64 + c*16 + kq*4];
            Ks[kq*4+0][m] = v.x; Ks[kq*4+1][m] = v.y;
            Ks[kq*4+2][m] = v.z; Ks[kq*4+3][m] = v.w;
        }
        __syncthreads();
        #pragma unroll
        for (int kk = 0; kk < 16; kk++) {
            float2 aa[4];
            #pragma unroll
            for (int i = 0; i < 4; i++) {
                float a = Qs[c*16+kk][w*4+i];
                aa[i] = make_float2(a, a);
            }
            #pragma unroll
            for (int jp = 0; jp < 8; jp++) {
                float2 bb = make_float2(Ks[kk][(2*jp)*32 + lane],
                                        Ks[kk][(2*jp+1)*32 + lane]);
                ffma2(acc[0][jp], aa[0], bb);
                ffma2(acc[1][jp], aa[1], bb);
                ffma2(acc[2][jp], aa[2], bb);
                ffma2(acc[3][jp], aa[3], bb);
            }
        }
    }
    #pragma unroll
    for (int i = 0; i < 4; i++) {
        int n = n0 + w*4 + i;
        const float* bp = &g_bias[((size_t)b*512 + n)*512 + lane];
        #pragma unroll
        for (int jp = 0; jp < 8; jp++) {
            acc[i][jp].x += bp[(2*jp)*32];
            acc[i][jp].y += bp[(2*jp+1)*32];
        }
        float mx = -INFINITY;
        #pragma unroll
        for (int jp = 0; jp < 8; jp++)
            mx = fmaxf(mx, fmaxf(acc[i][jp].x, acc[i][jp].y));
        #pragma unroll
        for (int off = 16; off > 0; off >>= 1)
            mx = fmaxf(mx, __shfl_xor_sync(0xffffffff, mx, off));
        float s = 0.f;
        #pragma unroll
        for (int jp = 0; jp < 8; jp++) {
            acc[i][jp].x = __expf(acc[i][jp].x - mx);
            acc[i][jp].y = __expf(acc[i][jp].y - mx);
            s += acc[i][jp].x + acc[i][jp].y;
        }
        #pragma unroll
        for (int off = 16; off > 0; off >>= 1)
            s += __shfl_xor_sync(0xffffffff, s, off);
        float inv = 1.f / s;
        float* pr = &g_p[((size_t)bh*512 + n)*512 + lane];
        #pragma unroll
        for (int jp = 0; jp < 8; jp++) {
            pr[(2*jp)*32]   = acc[i][jp].x * inv;
            pr[(2*jp+1)*32] = acc[i][jp].y * inv;
        }
    }
}

// ---------------- context: tf32 MMA, CTA 128x64 per (bh) -------------------
__global__ void __launch_bounds__(256) ctx_kernel() {
    __shared__ float As[2][4*PLA];
    __shared__ float Bs[2][4*PLB];
    int bh = blockIdx.y, b = bh >> 3, h = bh & 7;
    int n0 = blockIdx.x * 128;
    const float* p = g_p + (size_t)bh * 512 * 512;
    const float* v = g_v + (size_t)bh * 512 * 64;
    int tid = threadIdx.x, lane = tid & 31, w = tid >> 5;
    int warp_m = (w & 3) * 32, warp_n = (w >> 2) * 32;
    int r = lane >> 2, c = lane & 3;

    float4 acc[2][4];
    #pragma unroll
    for (int i = 0; i < 2; i++)
        #pragma unroll
        for (int j = 0; j < 4; j++) acc[i][j] = make_float4(0.f,0.f,0.f,0.f);

    #pragma unroll
    for (int t = 0; t < 8; t++) {
        int i = tid + 256*t; int kk = i & 15, m = i >> 4;
        cp4(&As[0][(kk & 3)*PLA + m*4 + (kk >> 2)], &p[(size_t)(n0 + m)*512 + kk]);
    }
    #pragma unroll
    for (int t = 0; t < 4; t++) {
        int i = tid + 256*t; int n = i & 63, kk = i >> 6;
        cp4(&Bs[0][(kk & 3)*PLB + n*4 + (kk >> 2)], &v[(size_t)kk*64 + n]);
    }
    cp_commit();

    for (int it = 0; it < 32; it++) {
        if (it < 31) {
            int k0 = (it + 1) * 16, buf = (it + 1) & 1;
            #pragma unroll
            for (int t = 0; t < 8; t++) {
                int i = tid + 256*t; int kk = i & 15, m = i >> 4;
                cp4(&As[buf][(kk & 3)*PLA + m*4 + (kk >> 2)], &p[(size_t)(n0 + m)*512 + k0 + kk]);
            }
            #pragma unroll
            for (int t = 0; t < 4; t++) {
                int i = tid + 256*t; int n = i & 63, kk = i >> 6;
                cp4(&Bs[buf][(kk & 3)*PLB + n*4 + (kk >> 2)], &v[(size_t)(k0 + kk)*64 + n]);
            }
            cp_commit();
            cp_wait1();
        } else cp_wait0();
        __syncthreads();
        const float* a = As[it & 1];
        const float* bsm = Bs[it & 1];
        unsigned bu[4][4];
        #pragma unroll
        for (int j = 0; j < 4; j++) {
            float4 vv = *(const float4*)&bsm[c*PLB + (warp_n + j*8 + r)*4];
            bu[j][0]=f2t(vv.x); bu[j][1]=f2t(vv.y); bu[j][2]=f2t(vv.z); bu[j][3]=f2t(vv.w);
        }
        #pragma unroll
        for (int i = 0; i < 2; i++) {
            float4 lo = *(const float4*)&a[c*PLA + (warp_m + i*16 + r)*4];
            float4 hi = *(const float4*)&a[c*PLA + (warp_m + i*16 + r + 8)*4];
            unsigned a00=f2t(lo.x), a01=f2t(lo.y), a02=f2t(lo.z), a03=f2t(lo.w);
            unsigned a10=f2t(hi.x), a11=f2t(hi.y), a12=f2t(hi.z), a13=f2t(hi.w);
            #pragma unroll
            for (int j = 0; j < 4; j++) {
                mma8(acc[i][j], a00, a10, a01, a11, bu[j][0], bu[j][1]);
                mma8(acc[i][j], a02, a12, a03, a13, bu[j][2], bu[j][3]);
            }
        }
        __syncthreads();
    }
    #pragma unroll
    for (int j = 0; j < 4; j++) {
        int dk = warp_n + j*8 + 2*c;
        #pragma unroll
        for (int i = 0; i < 2; i++) {
            float4 d = acc[i][j];
            int R0 = n0 + warp_m + i*16 + r;
            *(float2*)&g_s1[((size_t)b*512 + R0)*768 + h*64 + dk] = make_float2(d.x, d.y);
            *(float2*)&g_s1[((size_t)b*512 + R0 + 8)*768 + h*64 + dk] = make_float2(d.z, d.w);
        }
    }
}

// ---------------- E accumulation with smem-staged P (f32x2) ----------------
__global__ void __launch_bounds__(256) e_kernel(const float* __restrict__ edge) {
    __shared__ float sP[64*33];
    int tid = threadIdx.x;
    int h = tid & 7, np = (tid >> 3) & 7, es = tid >> 6;
    int b = blockIdx.y, n0 = blockIdx.x * 8;
    int n = n0 + np;
    int row = np*8 + h;
    const float* ep = edge + ((size_t)(b*512 + n) * 512) * 32 + es*8;
    float2 acc[4];
    #pragma unroll
    for (int j = 0; j < 4; j++) acc[j] = make_float2(0.f, 0.f);

    for (int c = 0; c < 16; c++) {
        __syncthreads();
        #pragma unroll
        for (int i = 0; i < 2; i++) {
            int idx = tid + 256*i;
            int r = idx >> 3, seg = idx & 7;
            int hh = r & 7, nn = r >> 3;
            float4 v = *(const float4*)&g_p[(((size_t)(b*8 + hh)*512) + n0 + nn)*512 + c*32 + seg*4];
            sP[r*33 + seg*4 + 0] = v.x; sP[r*33 + seg*4 + 1] = v.y;
            sP[r*33 + seg*4 + 2] = v.z; sP[r*33 + seg*4 + 3] = v.w;
        }
        __syncthreads();
        #pragma unroll 4
        for (int mm = 0; mm < 32; mm++) {
            float a = sP[row*33 + mm];
            float2 aa = make_float2(a, a);
            const float* e = ep + (size_t)(c*32 + mm) * 32;
            float4 e0 = *(const float4*)(e);
            float4 e1 = *(const float4*)(e + 4);
            ffma2(acc[0], aa, make_float2(e0.x, e0.y));
            ffma2(acc[1], aa, make_float2(e0.z, e0.w));
            ffma2(acc[2], aa, make_float2(e1.x, e1.y));
            ffma2(acc[3], aa, make_float2(e1.z, e1.w));
        }
    }
    float* o = &g_s1[((size_t)b*512 + n)*768 + 512 + h*32 + es*8];
    *(float4*)o     = make_float4(acc[0].x, acc[0].y, acc[1].x, acc[1].y);
    *(float4*)(o+4) = make_float4(acc[2].x, acc[2].y, acc[3].x, acc[3].y);
}

// ---------------- final GEMM: tf32 MMA, CTA 128x64 -------------------------
__global__ void __launch_bounds__(256) final_kernel(float* __restrict__ out) {
    __shared__ float As[2][4*PLA];
    __shared__ float Bs[2][4*PLB];
    int m0 = blockIdx.y * 128, n0 = blockIdx.x * 64;
    int tid = threadIdx.x, lane = tid & 31, w = tid >> 5;
    int warp_m = (w & 3) * 32, warp_n = (w >> 2) * 32;
    int r = lane >> 2, c = lane & 3;

    float4 acc[2][4];
    #pragma unroll
    for (int i = 0; i < 2; i++)
        #pragma unroll
        for (int j = 0; j < 4; j++) acc[i][j] = make_float4(0.f,0.f,0.f,0.f);

    #pragma unroll
    for (int t = 0; t < 8; t++) {
        int i = tid + 256*t; int kk = i & 15, m = i >> 4;
        cp4(&As[0][(kk & 3)*PLA + m*4 + (kk >> 2)], &g_s1[(size_t)(m0 + m)*768 + kk]);
    }
    #pragma unroll
    for (int t = 0; t < 4; t++) {
        int i = tid + 256*t; int kk = i & 15, n = i >> 4;
        cp4(&Bs[0][(kk & 3)*PLB + n*4 + (kk >> 2)], &g_wcomb[(size_t)(n0 + n)*768 + kk]);
    }
    cp_commit();

    for (int it = 0; it < 48; it++) {
        if (it < 47) {
            int k0 = (it + 1) * 16, buf = (it + 1) & 1;
            #pragma unroll
            for (int t = 0; t < 8; t++) {
                int i = tid + 256*t; int kk = i & 15, m = i >> 4;
                cp4(&As[buf][(kk & 3)*PLA + m*4 + (kk >> 2)], &g_s1[(size_t)(m0 + m)*768 + k0 + kk]);
            }
            #pragma unroll
            for (int t = 0; t < 4; t++) {
                int i = tid + 256*t; int kk = i & 15, n = i >> 4;
                cp4(&Bs[buf][(kk & 3)*PLB + n*4 + (kk >> 2)], &g_wcomb[(size_t)(n0 + n)*768 + k0 + kk]);
            }
            cp_commit();
            cp_wait1();
        } else cp_wait0();
        __syncthreads();
        const float* a = As[it & 1];
        const float* bsm = Bs[it & 1];
        unsigned bu[4][4];
        #pragma unroll
        for (int j = 0; j < 4; j++) {
            float4 vv = *(const float4*)&bsm[c*PLB + (warp_n + j*8 + r)*4];
            bu[j][0]=f2t(vv.x); bu[j][1]=f2t(vv.y); bu[j][2]=f2t(vv.z); bu[j][3]=f2t(vv.w);
        }
        #pragma unroll
        for (int i = 0; i < 2; i++) {
            float4 lo = *(const float4*)&a[c*PLA + (warp_m + i*16 + r)*4];
            float4 hi = *(const float4*)&a[c*PLA + (warp_m + i*16 + r + 8)*4];
            unsigned a00=f2t(lo.x), a01=f2t(lo.y), a02=f2t(lo.z), a03=f2t(lo.w);
            unsigned a10=f2t(hi.x), a11=f2t(hi.y), a12=f2t(hi.z), a13=f2t(hi.w);
            #pragma unroll
            for (int j = 0; j < 4; j++) {
                mma8(acc[i][j], a00, a10, a01, a11, bu[j][0], bu[j][1]);
                mma8(acc[i][j], a02, a12, a03, a13, bu[j][2], bu[j][3]);
            }
        }
        __syncthreads();
    }
    #pragma unroll
    for (int j = 0; j < 4; j++) {
        int np0 = n0 + warp_n + j*8 + 2*c;
        float b0v = g_bfinal[np0], b1v = g_bfinal[np0 + 1];
        #pragma unroll
        for (int i = 0; i < 2; i++) {
            float4 d = acc[i][j];
            int R0 = m0 + warp_m + i*16 + r;
            *(float2*)&out[(size_t)R0*512 + np0] = make_float2(d.x + b0v, d.y + b1v);
            *(float2*)&out[(size_t)(R0 + 8)*512 + np0] = make_float2(d.z + b0v, d.w + b1v);
        }
    }
}

extern "C" void kernel_launch(void* const* d_in, const int* in_sizes, int n_in,
                              void* d_out, int out_size) {
    const float* Q    = (const float*)d_in[0];
    const float* K    = (const float*)d_in[1];
    const float* V    = (const float*)d_in[2];
    const unsigned char* mask = (const unsigned char*)d_in[3];
    const float* edge = (const float*)d_in[4];
    const float* W_Q  = (const float*)d_in[5];
    const float* b_Q  = (const float*)d_in[6];
    const float* W_K  = (const float*)d_in[7];
    const float* b_K  = (const float*)d_in[8];
    const float* W_V  = (const float*)d_in[9];
    const float* b_V  = (const float*)d_in[10];
    const float* W_Ke = (const float*)d_in[11];
    const float* b_Ke = (const float*)d_in[12];
    const float* W_eb = (const float*)d_in[13];
    const float* b_eb = (const float*)d_in[14];
    const float* W_eo = (const float*)d_in[15];
    const float* b_eo = (const float*)d_in[16];
    const float* W_o  = (const float*)d_in[17];
    const float* b_o  = (const float*)d_in[18];
    float* out = (float*)d_out;

    prep1_kernel<<<512, 256>>>(W_Ke, b_Ke, W_eo, b_eo);
    prep2_kernel<<<512, 64>>>(W_o, b_o);
    proj_kernel<<<dim3(4, 16, 3), 256>>>(Q, K, V, W_Q, W_K, W_V, b_Q, b_K, b_V);
    biask_kernel<<<2048, 256>>>(edge, mask, W_eb, b_eb);
    scores_kernel<<<dim3(16, 32), 256>>>();
    ctx_kernel<<<dim3(4, 32), 256>>>();
    e_kernel<<<dim3(64, 4), 256>>>(edge);
    final_kernel<<<dim3(8, 16), 256>>>(out);
}

// round 8
// speedup vs baseline: 3.4411x; 1.2924x over previous
#include <cuda_runtime.h>
#include <math.h>
#include <stdint.h>

#define QSCALE 0.08838834764831845f   // (2*64)^-0.5
#define BSCALE 0.7071067811865476f    // 2^-0.5

// ---------------- device scratch ----------------
__device__ float g_q[4*8*512*64];
__device__ float g_k[4*8*512*64];
__device__ float g_v[4*8*512*64];
__device__ float g_bias[4*512*512];
__device__ float g_p[4*8*512*512];
__device__ float g_s1[4*512*768];      // [b*512+s][0:512 ctx | 512:768 E]
__device__ float g_wcomb[512*768];
__device__ float g_bfinal[512];
__device__ float g_M[512*256];
__device__ float g_c[512];

// ---------------- packed fp32x2 FMA ----------------
__device__ __forceinline__ void ffma2(float2& c, float2 a, float2 b) {
    unsigned long long ca = *reinterpret_cast<const unsigned long long*>(&a);
    unsigned long long cb = *reinterpret_cast<const unsigned long long*>(&b);
    unsigned long long cc = *reinterpret_cast<unsigned long long*>(&c);
    asm("fma.rn.f32x2 %0, %1, %2, %0;" : "+l"(cc) : "l"(ca), "l"(cb));
    *reinterpret_cast<unsigned long long*>(&c) = cc;
}

// ---------------- tf32 mma helpers ----------------
__device__ __forceinline__ unsigned f2t(float x) {
    unsigned u; asm("cvt.rna.tf32.f32 %0, %1;" : "=r"(u) : "f"(x)); return u;
}
__device__ __forceinline__ void mma8(float4& d, unsigned a0, unsigned a1, unsigned a2, unsigned a3,
                                     unsigned b0, unsigned b1) {
    asm volatile("mma.sync.aligned.m16n8k8.row.col.f32.tf32.tf32.f32 "
                 "{%0,%1,%2,%3},{%4,%5,%6,%7},{%8,%9},{%0,%1,%2,%3};"
                 : "+f"(d.x), "+f"(d.y), "+f"(d.z), "+f"(d.w)
                 : "r"(a0), "r"(a1), "r"(a2), "r"(a3), "r"(b0), "r"(b1));
}

// ---------------- cp.async helpers ----------------
__device__ __forceinline__ void cp4(void* s, const void* g) {
    unsigned sa = (unsigned)__cvta_generic_to_shared(s);
    asm volatile("cp.async.ca.shared.global [%0], [%1], 4;" :: "r"(sa), "l"(g));
}
__device__ __forceinline__ void cp_commit() { asm volatile("cp.async.commit_group;"); }
__device__ __forceinline__ void cp_wait1()  { asm volatile("cp.async.wait_group 1;"); }
__device__ __forceinline__ void cp_wait0()  { asm volatile("cp.async.wait_group 0;"); }

// 4-plane split layout: element (row m, k) lives at plane (k&3), offset m*4+(k>>2).
#define PLA 520   // 128-row planes
#define PLB 264   // 64-row planes

// ---------------- prep ----------------
__global__ void prep1_kernel(const float* __restrict__ W_Ke, const float* __restrict__ b_Ke,
                             const float* __restrict__ W_eo, const float* __restrict__ b_eo) {
    int d2 = blockIdx.x, j = threadIdx.x;
    int h = j >> 5, e = j & 31;
    const float* weo = W_eo + d2 * 256;
    float acc = 0.f;
    #pragma unroll
    for (int de = 0; de < 32; de++)
        acc = fmaf(weo[h*32 + de], W_Ke[de*32 + e], acc);
    g_M[d2*256 + j] = acc;
    if (j == 0) {
        float c = b_eo[d2];
        for (int jj = 0; jj < 256; jj++) c = fmaf(weo[jj], b_Ke[jj & 31], c);
        g_c[d2] = c;
    }
}

__global__ void prep2_kernel(const float* __restrict__ W_o, const float* __restrict__ b_o) {
    int d = blockIdx.x, j4 = threadIdx.x;   // 0..63
    const float* wo = W_o + (size_t)d * 1024;
    float4 acc = make_float4(0.f,0.f,0.f,0.f);
    float bacc = 0.f;
    #pragma unroll 4
    for (int d2 = 0; d2 < 512; d2++) {
        float wv = wo[512 + d2];
        float4 m = *(const float4*)&g_M[d2*256 + j4*4];
        acc.x = fmaf(wv, m.x, acc.x); acc.y = fmaf(wv, m.y, acc.y);
        acc.z = fmaf(wv, m.z, acc.z); acc.w = fmaf(wv, m.w, acc.w);
        if (j4 == 0) bacc = fmaf(wv, g_c[d2], bacc);
    }
    *(float4*)&g_wcomb[(size_t)d*768 + 512 + j4*4] = acc;
    #pragma unroll
    for (int t = 0; t < 8; t++)
        g_wcomb[(size_t)d*768 + j4*8 + t] = wo[j4*8 + t];
    if (j4 == 0) g_bfinal[d] = b_o[d] + bacc;
}

// ---------------- QKV projection: tf32 MMA, CTA 128x128 --------------------
__global__ void __launch_bounds__(256) proj_kernel(
    const float* __restrict__ Q, const float* __restrict__ K, const float* __restrict__ V,
    const float* __restrict__ WQ, const float* __restrict__ WK, const float* __restrict__ WV,
    const float* __restrict__ bQ, const float* __restrict__ bK, const float* __restrict__ bV) {
    __shared__ float As[2][4*PLA];
    __shared__ float Bs[2][4*PLA];
    int z = blockIdx.z;
    const float* A    = (z == 0) ? Q  : (z == 1) ? K  : V;
    const float* W    = (z == 0) ? WQ : (z == 1) ? WK : WV;
    const float* bias = (z == 0) ? bQ : (z == 1) ? bK : bV;
    float* dst        = (z == 0) ? g_q : (z == 1) ? g_k : g_v;
    int m0 = blockIdx.y * 128, n0 = blockIdx.x * 128;
    int tid = threadIdx.x, lane = tid & 31, w = tid >> 5;
    int warp_m = (w & 1) * 64, warp_n = (w >> 1) * 32;
    int r = lane >> 2, c = lane & 3;

    float4 acc[4][4];
    #pragma unroll
    for (int i = 0; i < 4; i++)
        #pragma unroll
        for (int j = 0; j < 4; j++) acc[i][j] = make_float4(0.f,0.f,0.f,0.f);

    #pragma unroll
    for (int t = 0; t < 8; t++) {
        int i = tid + 256*t; int kk = i & 15, m = i >> 4;
        int off = (kk & 3)*PLA + m*4 + (kk >> 2);
        cp4(&As[0][off], &A[(size_t)(m0 + m)*512 + kk]);
        cp4(&Bs[0][off], &W[(size_t)(n0 + m)*512 + kk]);
    }
    cp_commit();

    for (int it = 0; it < 32; it++) {
        if (it < 31) {
            int k0 = (it + 1) * 16, buf = (it + 1) & 1;
            #pragma unroll
            for (int t = 0; t < 8; t++) {
                int i = tid + 256*t; int kk = i & 15, m = i >> 4;
                int off = (kk & 3)*PLA + m*4 + (kk >> 2);
                cp4(&As[buf][off], &A[(size_t)(m0 + m)*512 + k0 + kk]);
                cp4(&Bs[buf][off], &W[(size_t)(n0 + m)*512 + k0 + kk]);
            }
            cp_commit();
            cp_wait1();
        } else cp_wait0();
        __syncthreads();
        const float* a = As[it & 1];
        const float* bsm = Bs[it & 1];
        unsigned bu[4][4];
        #pragma unroll
        for (int j = 0; j < 4; j++) {
            float4 v = *(const float4*)&bsm[c*PLA + (warp_n + j*8 + r)*4];
            bu[j][0]=f2t(v.x); bu[j][1]=f2t(v.y); bu[j][2]=f2t(v.z); bu[j][3]=f2t(v.w);
        }
        #pragma unroll
        for (int i = 0; i < 4; i++) {
            float4 lo = *(const float4*)&a[c*PLA + (warp_m + i*16 + r)*4];
            float4 hi = *(const float4*)&a[c*PLA + (warp_m + i*16 + r + 8)*4];
            unsigned a00=f2t(lo.x), a01=f2t(lo.y), a02=f2t(lo.z), a03=f2t(lo.w);
            unsigned a10=f2t(hi.x), a11=f2t(hi.y), a12=f2t(hi.z), a13=f2t(hi.w);
            #pragma unroll
            for (int j = 0; j < 4; j++) {
                mma8(acc[i][j], a00, a10, a01, a11, bu[j][0], bu[j][1]);
                mma8(acc[i][j], a02, a12, a03, a13, bu[j][2], bu[j][3]);
            }
        }
        __syncthreads();
    }
    float scale = (z == 0) ? QSCALE : 1.0f;
    #pragma unroll
    for (int j = 0; j < 4; j++) {
        int np0 = n0 + warp_n + j*8 + 2*c;
        int h = np0 >> 6, dk = np0 & 63;
        float b0v = bias[np0], b1v = bias[np0 + 1];
        #pragma unroll
        for (int i = 0; i < 4; i++) {
            float4 d = acc[i][j];
            int R0 = m0 + warp_m + i*16 + r;
            int R1 = R0 + 8;
            float2 o0 = make_float2((d.x + b0v)*scale, (d.y + b1v)*scale);
            float2 o1 = make_float2((d.z + b0v)*scale, (d.w + b1v)*scale);
            *(float2*)&dst[(((size_t)((R0 >> 9)*8 + h)*512 + (R0 & 511))*64) + dk] = o0;
            *(float2*)&dst[(((size_t)((R1 >> 9)*8 + h)*512 + (R1 & 511))*64) + dk] = o1;
        }
    }
}

// ---------------- edge bias + mask ----------------
__global__ void __launch_bounds__(256) biask_kernel(
    const float* __restrict__ edge, const unsigned char* __restrict__ mask,
    const float* __restrict__ W_eb, const float* __restrict__ b_eb) {
    __shared__ float w[32];
    __shared__ float b0s;
    if (threadIdx.x < 32) w[threadIdx.x] = W_eb[threadIdx.x];
    if (threadIdx.x == 0) b0s = b_eb[0];
    __syncthreads();
    int warp = threadIdx.x >> 5, lane = threadIdx.x & 31;
    int g = lane >> 3, sub = lane & 7;
    float w0 = w[sub*4], w1 = w[sub*4+1], w2 = w[sub*4+2], w3 = w[sub*4+3];
    size_t base = ((size_t)blockIdx.x * 8 + warp) * 64;
    for (int step = 0; step < 16; step++) {
        size_t pb = base + (size_t)step * 4;
        float4 ev = *(const float4*)(edge + (pb + g)*32 + sub*4);
        float t = ev.x*w0;
        t = fmaf(ev.y, w1, t); t = fmaf(ev.z, w2, t); t = fmaf(ev.w, w3, t);
        t += __shfl_xor_sync(0xffffffff, t, 4);
        t += __shfl_xor_sync(0xffffffff, t, 2);
        t += __shfl_xor_sync(0xffffffff, t, 1);
        if (sub == 0) {
            size_t p = pb + g;
            float r = (t + b0s) * BSCALE;
            g_bias[p] = mask[p] ? -INFINITY : r;
        }
    }
}

// ---------------- scores + softmax fused (fp32 scalar, f32x2) --------------
__global__ void __launch_bounds__(256) scores_kernel() {
    __shared__ float Qs[64][33];
    __shared__ float Ks[16][520];
    int bh = blockIdx.y, b = bh >> 3;
    int n0 = blockIdx.x * 32;
    const float* q = g_q + (size_t)bh * 512 * 64;
    const float* k = g_k + (size_t)bh * 512 * 64;
    int tid = threadIdx.x, w = tid >> 5, lane = tid & 31;

    for (int i = tid; i < 2048; i += 256) {
        int kk = i & 63, n = i >> 6;
        Qs[kk][n] = q[(size_t)(n0 + n)*64 + kk];
    }
    float2 acc[4][8];
    #pragma unroll
    for (int i = 0; i < 4; i++)
        #pragma unroll
        for (int j = 0; j < 8; j++) acc[i][j] = make_float2(0.f, 0.f);

    for (int c = 0; c < 4; c++) {
        __syncthreads();
        for (int i = tid; i < 2048; i += 256) {
            int kq = i & 3, m = i >> 2;
            float4 v = *(const float4*)&k[(size_t)m*64 + c*16 + kq*4];
            Ks[kq*4+0][m] = v.x; Ks[kq*4+1][m] = v.y;
            Ks[kq*4+2][m] = v.z; Ks[kq*4+3][m] = v.w;
        }
        __syncthreads();
        #pragma unroll
        for (int kk = 0; kk < 16; kk++) {
            float2 aa[4];
            #pragma unroll
            for (int i = 0; i < 4; i++) {
                float a = Qs[c*16+kk][w*4+i];
                aa[i] = make_float2(a, a);
            }
            #pragma unroll
            for (int jp = 0; jp < 8; jp++) {
                float2 bb = make_float2(Ks[kk][(2*jp)*32 + lane],
                                        Ks[kk][(2*jp+1)*32 + lane]);
                ffma2(acc[0][jp], aa[0], bb);
                ffma2(acc[1][jp], aa[1], bb);
                ffma2(acc[2][jp], aa[2], bb);
                ffma2(acc[3][jp], aa[3], bb);
            }
        }
    }
    #pragma unroll
    for (int i = 0; i < 4; i++) {
        int n = n0 + w*4 + i;
        const float* bp = &g_bias[((size_t)b*512 + n)*512 + lane];
        #pragma unroll
        for (int jp = 0; jp < 8; jp++) {
            acc[i][jp].x += bp[(2*jp)*32];
            acc[i][jp].y += bp[(2*jp+1)*32];
        }
        float mx = -INFINITY;
        #pragma unroll
        for (int jp = 0; jp < 8; jp++)
            mx = fmaxf(mx, fmaxf(acc[i][jp].x, acc[i][jp].y));
        #pragma unroll
        for (int off = 16; off > 0; off >>= 1)
            mx = fmaxf(mx, __shfl_xor_sync(0xffffffff, mx, off));
        float s = 0.f;
        #pragma unroll
        for (int jp = 0; jp < 8; jp++) {
            acc[i][jp].x = __expf(acc[i][jp].x - mx);
            acc[i][jp].y = __expf(acc[i][jp].y - mx);
            s += acc[i][jp].x + acc[i][jp].y;
        }
        #pragma unroll
        for (int off = 16; off > 0; off >>= 1)
            s += __shfl_xor_sync(0xffffffff, s, off);
        float inv = 1.f / s;
        float* pr = &g_p[((size_t)bh*512 + n)*512 + lane];
        #pragma unroll
        for (int jp = 0; jp < 8; jp++) {
            pr[(2*jp)*32]   = acc[i][jp].x * inv;
            pr[(2*jp+1)*32] = acc[i][jp].y * inv;
        }
    }
}

// ---------------- context: tf32 MMA, CTA 64x64, 128 thr, grid (8,32) -------
__global__ void __launch_bounds__(128) ctx_kernel() {
    __shared__ float As[2][4*PLB];
    __shared__ float Bs[2][4*PLB];
    int bh = blockIdx.y, b = bh >> 3, h = bh & 7;
    int n0 = blockIdx.x * 64;
    const float* p = g_p + (size_t)bh * 512 * 512;
    const float* v = g_v + (size_t)bh * 512 * 64;
    int tid = threadIdx.x, lane = tid & 31, w = tid >> 5;
    int warp_m = (w & 1) * 32, warp_n = (w >> 1) * 32;
    int r = lane >> 2, c = lane & 3;

    float4 acc[2][4];
    #pragma unroll
    for (int i = 0; i < 2; i++)
        #pragma unroll
        for (int j = 0; j < 4; j++) acc[i][j] = make_float4(0.f,0.f,0.f,0.f);

    #pragma unroll
    for (int t = 0; t < 8; t++) {
        int i = tid + 128*t; int kk = i & 15, m = i >> 4;
        cp4(&As[0][(kk & 3)*PLB + m*4 + (kk >> 2)], &p[(size_t)(n0 + m)*512 + kk]);
    }
    #pragma unroll
    for (int t = 0; t < 8; t++) {
        int i = tid + 128*t; int n = i & 63, kk = i >> 6;
        cp4(&Bs[0][(kk & 3)*PLB + n*4 + (kk >> 2)], &v[(size_t)kk*64 + n]);
    }
    cp_commit();

    for (int it = 0; it < 32; it++) {
        if (it < 31) {
            int k0 = (it + 1) * 16, buf = (it + 1) & 1;
            #pragma unroll
            for (int t = 0; t < 8; t++) {
                int i = tid + 128*t; int kk = i & 15, m = i >> 4;
                cp4(&As[buf][(kk & 3)*PLB + m*4 + (kk >> 2)], &p[(size_t)(n0 + m)*512 + k0 + kk]);
            }
            #pragma unroll
            for (int t = 0; t < 8; t++) {
                int i = tid + 128*t; int n = i & 63, kk = i >> 6;
                cp4(&Bs[buf][(kk & 3)*PLB + n*4 + (kk >> 2)], &v[(size_t)(k0 + kk)*64 + n]);
            }
            cp_commit();
            cp_wait1();
        } else cp_wait0();
        __syncthreads();
        const float* a = As[it & 1];
        const float* bsm = Bs[it & 1];
        unsigned bu[4][4];
        #pragma unroll
        for (int j = 0; j < 4; j++) {
            float4 vv = *(const float4*)&bsm[c*PLB + (warp_n + j*8 + r)*4];
            bu[j][0]=f2t(vv.x); bu[j][1]=f2t(vv.y); bu[j][2]=f2t(vv.z); bu[j][3]=f2t(vv.w);
        }
        #pragma unroll
        for (int i = 0; i < 2; i++) {
            float4 lo = *(const float4*)&a[c*PLB + (warp_m + i*16 + r)*4];
            float4 hi = *(const float4*)&a[c*PLB + (warp_m + i*16 + r + 8)*4];
            unsigned a00=f2t(lo.x), a01=f2t(lo.y), a02=f2t(lo.z), a03=f2t(lo.w);
            unsigned a10=f2t(hi.x), a11=f2t(hi.y), a12=f2t(hi.z), a13=f2t(hi.w);
            #pragma unroll
            for (int j = 0; j < 4; j++) {
                mma8(acc[i][j], a00, a10, a01, a11, bu[j][0], bu[j][1]);
                mma8(acc[i][j], a02, a12, a03, a13, bu[j][2], bu[j][3]);
            }
        }
        __syncthreads();
    }
    #pragma unroll
    for (int j = 0; j < 4; j++) {
        int dk = warp_n + j*8 + 2*c;
        #pragma unroll
        for (int i = 0; i < 2; i++) {
            float4 d = acc[i][j];
            int R0 = n0 + warp_m + i*16 + r;
            *(float2*)&g_s1[((size_t)b*512 + R0)*768 + h*64 + dk] = make_float2(d.x, d.y);
            *(float2*)&g_s1[((size_t)b*512 + R0 + 8)*768 + h*64 + dk] = make_float2(d.z, d.w);
        }
    }
}

// ---------------- E accumulation: warp = n-row, lanes = e ------------------
// sP stride 68 (multiple of 4 -> float4-aligned reads; reads are broadcast)
__global__ void __launch_bounds__(256) e_kernel(const float* __restrict__ edge) {
    __shared__ float sP[32*68];   // [mm][np*8+h]
    int tid = threadIdx.x;
    int np = tid >> 5, e = tid & 31;
    int b = blockIdx.y, n0 = blockIdx.x * 8;
    int n = n0 + np;
    const float* ep = edge + ((size_t)(b*512 + n) * 512) * 32 + e;
    float2 acc[4];
    #pragma unroll
    for (int j = 0; j < 4; j++) acc[j] = make_float2(0.f, 0.f);

    for (int c = 0; c < 16; c++) {
        __syncthreads();
        #pragma unroll
        for (int i = 0; i < 2; i++) {
            int idx = tid + 256*i;
            int rr = idx >> 3, seg = idx & 7;
            int hh = rr & 7, nn = rr >> 3;
            float4 v = *(const float4*)&g_p[(((size_t)(b*8 + hh)*512) + n0 + nn)*512 + c*32 + seg*4];
            sP[(seg*4+0)*68 + nn*8 + hh] = v.x;
            sP[(seg*4+1)*68 + nn*8 + hh] = v.y;
            sP[(seg*4+2)*68 + nn*8 + hh] = v.z;
            sP[(seg*4+3)*68 + nn*8 + hh] = v.w;
        }
        __syncthreads();
        #pragma unroll 4
        for (int mm = 0; mm < 32; mm++) {
            float ev = __ldg(ep + (size_t)(c*32 + mm) * 32);
            float2 ee = make_float2(ev, ev);
            float4 p0 = *(const float4*)&sP[mm*68 + np*8];
            float4 p1 = *(const float4*)&sP[mm*68 + np*8 + 4];
            ffma2(acc[0], make_float2(p0.x, p0.y), ee);
            ffma2(acc[1], make_float2(p0.z, p0.w), ee);
            ffma2(acc[2], make_float2(p1.x, p1.y), ee);
            ffma2(acc[3], make_float2(p1.z, p1.w), ee);
        }
    }
    float* o = &g_s1[((size_t)b*512 + n)*768 + 512];
    o[0*32 + e] = acc[0].x; o[1*32 + e] = acc[0].y;
    o[2*32 + e] = acc[1].x; o[3*32 + e] = acc[1].y;
    o[4*32 + e] = acc[2].x; o[5*32 + e] = acc[2].y;
    o[6*32 + e] = acc[3].x; o[7*32 + e] = acc[3].y;
}

// ---------------- final GEMM: tf32 MMA, CTA 64x64, 128 thr, grid (8,32) ----
__global__ void __launch_bounds__(128) final_kernel(float* __restrict__ out) {
    __shared__ float As[2][4*PLB];
    __shared__ float Bs[2][4*PLB];
    int m0 = blockIdx.y * 64, n0 = blockIdx.x * 64;
    int tid = threadIdx.x, lane = tid & 31, w = tid >> 5;
    int warp_m = (w & 1) * 32, warp_n = (w >> 1) * 32;
    int r = lane >> 2, c = lane & 3;

    float4 acc[2][4];
    #pragma unroll
    for (int i = 0; i < 2; i++)
        #pragma unroll
        for (int j = 0; j < 4; j++) acc[i][j] = make_float4(0.f,0.f,0.f,0.f);

    #pragma unroll
    for (int t = 0; t < 8; t++) {
        int i = tid + 128*t; int kk = i & 15, m = i >> 4;
        cp4(&As[0][(kk & 3)*PLB + m*4 + (kk >> 2)], &g_s1[(size_t)(m0 + m)*768 + kk]);
        cp4(&Bs[0][(kk & 3)*PLB + m*4 + (kk >> 2)], &g_wcomb[(size_t)(n0 + m)*768 + kk]);
    }
    cp_commit();

    for (int it = 0; it < 48; it++) {
        if (it < 47) {
            int k0 = (it + 1) * 16, buf = (it + 1) & 1;
            #pragma unroll
            for (int t = 0; t < 8; t++) {
                int i = tid + 128*t; int kk = i & 15, m = i >> 4;
                cp4(&As[buf][(kk & 3)*PLB + m*4 + (kk >> 2)], &g_s1[(size_t)(m0 + m)*768 + k0 + kk]);
                cp4(&Bs[buf][(kk & 3)*PLB + m*4 + (kk >> 2)], &g_wcomb[(size_t)(n0 + m)*768 + k0 + kk]);
            }
            cp_commit();
            cp_wait1();
        } else cp_wait0();
        __syncthreads();
        const float* a = As[it & 1];
        const float* bsm = Bs[it & 1];
        unsigned bu[4][4];
        #pragma unroll
        for (int j = 0; j < 4; j++) {
            float4 vv = *(const float4*)&bsm[c*PLB + (warp_n + j*8 + r)*4];
            bu[j][0]=f2t(vv.x); bu[j][1]=f2t(vv.y); bu[j][2]=f2t(vv.z); bu[j][3]=f2t(vv.w);
        }
        #pragma unroll
        for (int i = 0; i < 2; i++) {
            float4 lo = *(const float4*)&a[c*PLB + (warp_m + i*16 + r)*4];
            float4 hi = *(const float4*)&a[c*PLB + (warp_m + i*16 + r + 8)*4];
            unsigned a00=f2t(lo.x), a01=f2t(lo.y), a02=f2t(lo.z), a03=f2t(lo.w);
            unsigned a10=f2t(hi.x), a11=f2t(hi.y), a12=f2t(hi.z), a13=f2t(hi.w);
            #pragma unroll
            for (int j = 0; j < 4; j++) {
                mma8(acc[i][j], a00, a10, a01, a11, bu[j][0], bu[j][1]);
                mma8(acc[i][j], a02, a12, a03, a13, bu[j][2], bu[j][3]);
            }
        }
        __syncthreads();
    }
    #pragma unroll
    for (int j = 0; j < 4; j++) {
        int np0 = n0 + warp_n + j*8 + 2*c;
        float b0v = g_bfinal[np0], b1v = g_bfinal[np0 + 1];
        #pragma unroll
        for (int i = 0; i < 2; i++) {
            float4 d = acc[i][j];
            int R0 = m0 + warp_m + i*16 + r;
            *(float2*)&out[(size_t)R0*512 + np0] = make_float2(d.x + b0v, d.y + b1v);
            *(float2*)&out[(size_t)(R0 + 8)*512 + np0] = make_float2(d.z + b0v, d.w + b1v);
        }
    }
}

extern "C" void kernel_launch(void* const* d_in, const int* in_sizes, int n_in,
                              void* d_out, int out_size) {
    const float* Q    = (const float*)d_in[0];
    const float* K    = (const float*)d_in[1];
    const float* V    = (const float*)d_in[2];
    const unsigned char* mask = (const unsigned char*)d_in[3];
    const float* edge = (const float*)d_in[4];
    const float* W_Q  = (const float*)d_in[5];
    const float* b_Q  = (const float*)d_in[6];
    const float* W_K  = (const float*)d_in[7];
    const float* b_K  = (const float*)d_in[8];
    const float* W_V  = (const float*)d_in[9];
    const float* b_V  = (const float*)d_in[10];
    const float* W_Ke = (const float*)d_in[11];
    const float* b_Ke = (const float*)d_in[12];
    const float* W_eb = (const float*)d_in[13];
    const float* b_eb = (const float*)d_in[14];
    const float* W_eo = (const float*)d_in[15];
    const float* b_eo = (const float*)d_in[16];
    const float* W_o  = (const float*)d_in[17];
    const float* b_o  = (const float*)d_in[18];
    float* out = (float*)d_out;

    static cudaStream_t s1 = nullptr;
    static cudaEvent_t evF, evB, evS, evE;
    if (!s1) {
        cudaStreamCreateWithFlags(&s1, cudaStreamNonBlocking);
        cudaEventCreateWithFlags(&evF, cudaEventDisableTiming);
        cudaEventCreateWithFlags(&evB, cudaEventDisableTiming);
        cudaEventCreateWithFlags(&evS, cudaEventDisableTiming);
        cudaEventCreateWithFlags(&evE, cudaEventDisableTiming);
    }

    // fork: biask (DRAM-bound) on s1  ||  prep + proj (tensor-bound) on main
    cudaEventRecord(evF, 0);
    cudaStreamWaitEvent(s1, evF, 0);
    biask_kernel<<<2048, 256, 0, s1>>>(edge, mask, W_eb, b_eb);
    prep1_kernel<<<512, 256>>>(W_Ke, b_Ke, W_eo, b_eo);
    prep2_kernel<<<512, 64>>>(W_o, b_o);
    proj_kernel<<<dim3(4, 16, 3), 256>>>(Q, K, V, W_Q, W_K, W_V, b_Q, b_K, b_V);
    cudaEventRecord(evB, s1);
    cudaStreamWaitEvent(0, evB, 0);

    scores_kernel<<<dim3(16, 32), 256>>>();

    // fork: e (DRAM-bound) on s1  ||  ctx (tensor-bound) on main
    cudaEventRecord(evS, 0);
    cudaStreamWaitEvent(s1, evS, 0);
    e_kernel<<<dim3(64, 4), 256, 0, s1>>>(edge);
    ctx_kernel<<<dim3(8, 32), 128>>>();
    cudaEventRecord(evE, s1);
    cudaStreamWaitEvent(0, evE, 0);

    final_kernel<<<dim3(8, 32), 128>>>(out);
}

// round 9
// speedup vs baseline: 4.1859x; 1.2165x over previous
#include <cuda_runtime.h>
#include <math.h>
#include <stdint.h>

#define QSCALE 0.08838834764831845f   // (2*64)^-0.5
#define BSCALE 0.7071067811865476f    // 2^-0.5

// ---------------- device scratch ----------------
__device__ float g_q[4*8*512*64];
__device__ float g_k[4*8*512*64];
__device__ float g_v[4*8*512*64];
__device__ float g_bias[4*512*512];
__device__ float g_p[4*8*512*512];
__device__ float g_s1[4*512*768];      // [b*512+s][0:512 ctx | 512:768 E]
__device__ float g_wcomb[512*768];
__device__ float g_bfinal[512];
__device__ float g_M[512*256];
__device__ float g_c[512];

// ---------------- packed fp32x2 FMA ----------------
__device__ __forceinline__ void ffma2(float2& c, float2 a, float2 b) {
    unsigned long long ca = *reinterpret_cast<const unsigned long long*>(&a);
    unsigned long long cb = *reinterpret_cast<const unsigned long long*>(&b);
    unsigned long long cc = *reinterpret_cast<unsigned long long*>(&c);
    asm("fma.rn.f32x2 %0, %1, %2, %0;" : "+l"(cc) : "l"(ca), "l"(cb));
    *reinterpret_cast<unsigned long long*>(&c) = cc;
}

// ---------------- tf32 mma helpers ----------------
__device__ __forceinline__ unsigned f2t(float x) {
    unsigned u; asm("cvt.rna.tf32.f32 %0, %1;" : "=r"(u) : "f"(x)); return u;
}
__device__ __forceinline__ void mma8(float4& d, unsigned a0, unsigned a1, unsigned a2, unsigned a3,
                                     unsigned b0, unsigned b1) {
    asm volatile("mma.sync.aligned.m16n8k8.row.col.f32.tf32.tf32.f32 "
                 "{%0,%1,%2,%3},{%4,%5,%6,%7},{%8,%9},{%0,%1,%2,%3};"
                 : "+f"(d.x), "+f"(d.y), "+f"(d.z), "+f"(d.w)
                 : "r"(a0), "r"(a1), "r"(a2), "r"(a3), "r"(b0), "r"(b1));
}

// ---------------- cp.async helpers ----------------
__device__ __forceinline__ void cp4(void* s, const void* g) {
    unsigned sa = (unsigned)__cvta_generic_to_shared(s);
    asm volatile("cp.async.ca.shared.global [%0], [%1], 4;" :: "r"(sa), "l"(g));
}
__device__ __forceinline__ void cp_commit() { asm volatile("cp.async.commit_group;"); }
__device__ __forceinline__ void cp_wait1()  { asm volatile("cp.async.wait_group 1;"); }
__device__ __forceinline__ void cp_wait0()  { asm volatile("cp.async.wait_group 0;"); }

// 4-plane split layout: element (row m, k) lives at plane (k&3), offset m*4+(k>>2).
#define PLB 264   // 64-row planes

// ---------------- prep ----------------
__global__ void prep1_kernel(const float* __restrict__ W_Ke, const float* __restrict__ b_Ke,
                             const float* __restrict__ W_eo, const float* __restrict__ b_eo) {
    int d2 = blockIdx.x, j = threadIdx.x;
    int h = j >> 5, e = j & 31;
    const float* weo = W_eo + d2 * 256;
    float acc = 0.f;
    #pragma unroll
    for (int de = 0; de < 32; de++)
        acc = fmaf(weo[h*32 + de], W_Ke[de*32 + e], acc);
    g_M[d2*256 + j] = acc;
    if (j == 0) {
        float c = b_eo[d2];
        for (int jj = 0; jj < 256; jj++) c = fmaf(weo[jj], b_Ke[jj & 31], c);
        g_c[d2] = c;
    }
}

__global__ void prep2_kernel(const float* __restrict__ W_o, const float* __restrict__ b_o) {
    int d = blockIdx.x, j4 = threadIdx.x;   // 0..63
    const float* wo = W_o + (size_t)d * 1024;
    float4 acc = make_float4(0.f,0.f,0.f,0.f);
    float bacc = 0.f;
    #pragma unroll 4
    for (int d2 = 0; d2 < 512; d2++) {
        float wv = wo[512 + d2];
        float4 m = *(const float4*)&g_M[d2*256 + j4*4];
        acc.x = fmaf(wv, m.x, acc.x); acc.y = fmaf(wv, m.y, acc.y);
        acc.z = fmaf(wv, m.z, acc.z); acc.w = fmaf(wv, m.w, acc.w);
        if (j4 == 0) bacc = fmaf(wv, g_c[d2], bacc);
    }
    *(float4*)&g_wcomb[(size_t)d*768 + 512 + j4*4] = acc;
    #pragma unroll
    for (int t = 0; t < 8; t++)
        g_wcomb[(size_t)d*768 + j4*8 + t] = wo[j4*8 + t];
    if (j4 == 0) g_bfinal[d] = b_o[d] + bacc;
}

// ---------------- QKV projection: tf32 MMA, CTA 64x64, 128 thr -------------
// grid (8, 32, 3): (n-tile=head, m-tile, matrix)
__global__ void __launch_bounds__(128) proj_kernel(
    const float* __restrict__ Q, const float* __restrict__ K, const float* __restrict__ V,
    const float* __restrict__ WQ, const float* __restrict__ WK, const float* __restrict__ WV,
    const float* __restrict__ bQ, const float* __restrict__ bK, const float* __restrict__ bV) {
    __shared__ float As[2][4*PLB];
    __shared__ float Bs[2][4*PLB];
    int z = blockIdx.z;
    const float* A    = (z == 0) ? Q  : (z == 1) ? K  : V;
    const float* W    = (z == 0) ? WQ : (z == 1) ? WK : WV;
    const float* bias = (z == 0) ? bQ : (z == 1) ? bK : bV;
    float* dst        = (z == 0) ? g_q : (z == 1) ? g_k : g_v;
    int m0 = blockIdx.y * 64, n0 = blockIdx.x * 64;
    int tid = threadIdx.x, lane = tid & 31, w = tid >> 5;
    int warp_m = (w & 1) * 32, warp_n = (w >> 1) * 32;
    int r = lane >> 2, c = lane & 3;
    int h = blockIdx.x;   // n0/64

    float4 acc[2][4];
    #pragma unroll
    for (int i = 0; i < 2; i++)
        #pragma unroll
        for (int j = 0; j < 4; j++) acc[i][j] = make_float4(0.f,0.f,0.f,0.f);

    #pragma unroll
    for (int t = 0; t < 8; t++) {
        int i = tid + 128*t; int kk = i & 15, m = i >> 4;
        cp4(&As[0][(kk & 3)*PLB + m*4 + (kk >> 2)], &A[(size_t)(m0 + m)*512 + kk]);
        cp4(&Bs[0][(kk & 3)*PLB + m*4 + (kk >> 2)], &W[(size_t)(n0 + m)*512 + kk]);
    }
    cp_commit();

    for (int it = 0; it < 32; it++) {
        if (it < 31) {
            int k0 = (it + 1) * 16, buf = (it + 1) & 1;
            #pragma unroll
            for (int t = 0; t < 8; t++) {
                int i = tid + 128*t; int kk = i & 15, m = i >> 4;
                cp4(&As[buf][(kk & 3)*PLB + m*4 + (kk >> 2)], &A[(size_t)(m0 + m)*512 + k0 + kk]);
                cp4(&Bs[buf][(kk & 3)*PLB + m*4 + (kk >> 2)], &W[(size_t)(n0 + m)*512 + k0 + kk]);
            }
            cp_commit();
            cp_wait1();
        } else cp_wait0();
        __syncthreads();
        const float* a = As[it & 1];
        const float* bsm = Bs[it & 1];
        unsigned bu[4][4];
        #pragma unroll
        for (int j = 0; j < 4; j++) {
            float4 vv = *(const float4*)&bsm[c*PLB + (warp_n + j*8 + r)*4];
            bu[j][0]=f2t(vv.x); bu[j][1]=f2t(vv.y); bu[j][2]=f2t(vv.z); bu[j][3]=f2t(vv.w);
        }
        #pragma unroll
        for (int i = 0; i < 2; i++) {
            float4 lo = *(const float4*)&a[c*PLB + (warp_m + i*16 + r)*4];
            float4 hi = *(const float4*)&a[c*PLB + (warp_m + i*16 + r + 8)*4];
            unsigned a00=f2t(lo.x), a01=f2t(lo.y), a02=f2t(lo.z), a03=f2t(lo.w);
            unsigned a10=f2t(hi.x), a11=f2t(hi.y), a12=f2t(hi.z), a13=f2t(hi.w);
            #pragma unroll
            for (int j = 0; j < 4; j++) {
                mma8(acc[i][j], a00, a10, a01, a11, bu[j][0], bu[j][1]);
                mma8(acc[i][j], a02, a12, a03, a13, bu[j][2], bu[j][3]);
            }
        }
        __syncthreads();
    }
    float scale = (z == 0) ? QSCALE : 1.0f;
    #pragma unroll
    for (int j = 0; j < 4; j++) {
        int dk = warp_n + j*8 + 2*c;
        float b0v = bias[n0 + dk], b1v = bias[n0 + dk + 1];
        #pragma unroll
        for (int i = 0; i < 2; i++) {
            float4 d = acc[i][j];
            int R0 = m0 + warp_m + i*16 + r;
            int R1 = R0 + 8;
            float2 o0 = make_float2((d.x + b0v)*scale, (d.y + b1v)*scale);
            float2 o1 = make_float2((d.z + b0v)*scale, (d.w + b1v)*scale);
            *(float2*)&dst[(((size_t)((R0 >> 9)*8 + h)*512 + (R0 & 511))*64) + dk] = o0;
            *(float2*)&dst[(((size_t)((R1 >> 9)*8 + h)*512 + (R1 & 511))*64) + dk] = o1;
        }
    }
}

// ---------------- edge bias + mask ----------------
__global__ void __launch_bounds__(256) biask_kernel(
    const float* __restrict__ edge, const unsigned char* __restrict__ mask,
    const float* __restrict__ W_eb, const float* __restrict__ b_eb) {
    __shared__ float w[32];
    __shared__ float b0s;
    if (threadIdx.x < 32) w[threadIdx.x] = W_eb[threadIdx.x];
    if (threadIdx.x == 0) b0s = b_eb[0];
    __syncthreads();
    int warp = threadIdx.x >> 5, lane = threadIdx.x & 31;
    int g = lane >> 3, sub = lane & 7;
    float w0 = w[sub*4], w1 = w[sub*4+1], w2 = w[sub*4+2], w3 = w[sub*4+3];
    size_t base = ((size_t)blockIdx.x * 8 + warp) * 64;
    for (int step = 0; step < 16; step++) {
        size_t pb = base + (size_t)step * 4;
        float4 ev = *(const float4*)(edge + (pb + g)*32 + sub*4);
        float t = ev.x*w0;
        t = fmaf(ev.y, w1, t); t = fmaf(ev.z, w2, t); t = fmaf(ev.w, w3, t);
        t += __shfl_xor_sync(0xffffffff, t, 4);
        t += __shfl_xor_sync(0xffffffff, t, 2);
        t += __shfl_xor_sync(0xffffffff, t, 1);
        if (sub == 0) {
            size_t p = pb + g;
            float r = (t + b0s) * BSCALE;
            g_bias[p] = mask[p] ? -INFINITY : r;
        }
    }
}

// ---------------- scores + softmax fused (f32x2, paired columns) -----------
// CTA = 32 rows x 512 cols; lane owns column pairs jp*64 + lane*2 (+1).
__global__ void __launch_bounds__(256) scores_kernel() {
    __shared__ float Qs[64][33];
    __shared__ float Ks[16][520];
    int bh = blockIdx.y, b = bh >> 3;
    int n0 = blockIdx.x * 32;
    const float* q = g_q + (size_t)bh * 512 * 64;
    const float* k = g_k + (size_t)bh * 512 * 64;
    int tid = threadIdx.x, w = tid >> 5, lane = tid & 31;

    for (int i = tid; i < 2048; i += 256) {
        int kk = i & 63, n = i >> 6;
        Qs[kk][n] = q[(size_t)(n0 + n)*64 + kk];
    }
    float2 acc[4][8];   // [row i][jp]: cols jp*64 + lane*2, +1
    #pragma unroll
    for (int i = 0; i < 4; i++)
        #pragma unroll
        for (int j = 0; j < 8; j++) acc[i][j] = make_float2(0.f, 0.f);

    for (int c = 0; c < 4; c++) {
        __syncthreads();
        for (int i = tid; i < 2048; i += 256) {
            int kq = i & 3, m = i >> 2;
            float4 v = *(const float4*)&k[(size_t)m*64 + c*16 + kq*4];
            Ks[kq*4+0][m] = v.x; Ks[kq*4+1][m] = v.y;
            Ks[kq*4+2][m] = v.z; Ks[kq*4+3][m] = v.w;
        }
        __syncthreads();
        #pragma unroll
        for (int kk = 0; kk < 16; kk++) {
            float2 aa[4];
            #pragma unroll
            for (int i = 0; i < 4; i++) {
                float a = Qs[c*16+kk][w*4+i];
                aa[i] = make_float2(a, a);
            }
            #pragma unroll
            for (int jp = 0; jp < 8; jp++) {
                float2 bb = *(const float2*)&Ks[kk][jp*64 + lane*2];
                ffma2(acc[0][jp], aa[0], bb);
                ffma2(acc[1][jp], aa[1], bb);
                ffma2(acc[2][jp], aa[2], bb);
                ffma2(acc[3][jp], aa[3], bb);
            }
        }
    }
    #pragma unroll
    for (int i = 0; i < 4; i++) {
        int n = n0 + w*4 + i;
        const float* bp = &g_bias[((size_t)b*512 + n)*512];
        #pragma unroll
        for (int jp = 0; jp < 8; jp++) {
            float2 bb = *(const float2*)&bp[jp*64 + lane*2];
            acc[i][jp].x += bb.x;
            acc[i][jp].y += bb.y;
        }
        float mx = -INFINITY;
        #pragma unroll
        for (int jp = 0; jp < 8; jp++)
            mx = fmaxf(mx, fmaxf(acc[i][jp].x, acc[i][jp].y));
        #pragma unroll
        for (int off = 16; off > 0; off >>= 1)
            mx = fmaxf(mx, __shfl_xor_sync(0xffffffff, mx, off));
        float s = 0.f;
        #pragma unroll
        for (int jp = 0; jp < 8; jp++) {
            acc[i][jp].x = __expf(acc[i][jp].x - mx);
            acc[i][jp].y = __expf(acc[i][jp].y - mx);
            s += acc[i][jp].x + acc[i][jp].y;
        }
        #pragma unroll
        for (int off = 16; off > 0; off >>= 1)
            s += __shfl_xor_sync(0xffffffff, s, off);
        float inv = 1.f / s;
        float* pr = &g_p[((size_t)bh*512 + n)*512];
        #pragma unroll
        for (int jp = 0; jp < 8; jp++) {
            float2 o = make_float2(acc[i][jp].x * inv, acc[i][jp].y * inv);
            *(float2*)&pr[jp*64 + lane*2] = o;
        }
    }
}

// ---------------- context: tf32 MMA, CTA 64x64, 128 thr, grid (8,32) -------
__global__ void __launch_bounds__(128) ctx_kernel() {
    __shared__ float As[2][4*PLB];
    __shared__ float Bs[2][4*PLB];
    int bh = blockIdx.y, b = bh >> 3, h = bh & 7;
    int n0 = blockIdx.x * 64;
    const float* p = g_p + (size_t)bh * 512 * 512;
    const float* v = g_v + (size_t)bh * 512 * 64;
    int tid = threadIdx.x, lane = tid & 31, w = tid >> 5;
    int warp_m = (w & 1) * 32, warp_n = (w >> 1) * 32;
    int r = lane >> 2, c = lane & 3;

    float4 acc[2][4];
    #pragma unroll
    for (int i = 0; i < 2; i++)
        #pragma unroll
        for (int j = 0; j < 4; j++) acc[i][j] = make_float4(0.f,0.f,0.f,0.f);

    #pragma unroll
    for (int t = 0; t < 8; t++) {
        int i = tid + 128*t; int kk = i & 15, m = i >> 4;
        cp4(&As[0][(kk & 3)*PLB + m*4 + (kk >> 2)], &p[(size_t)(n0 + m)*512 + kk]);
    }
    #pragma unroll
    for (int t = 0; t < 8; t++) {
        int i = tid + 128*t; int n = i & 63, kk = i >> 6;
        cp4(&Bs[0][(kk & 3)*PLB + n*4 + (kk >> 2)], &v[(size_t)kk*64 + n]);
    }
    cp_commit();

    for (int it = 0; it < 32; it++) {
        if (it < 31) {
            int k0 = (it + 1) * 16, buf = (it + 1) & 1;
            #pragma unroll
            for (int t = 0; t < 8; t++) {
                int i = tid + 128*t; int kk = i & 15, m = i >> 4;
                cp4(&As[buf][(kk & 3)*PLB + m*4 + (kk >> 2)], &p[(size_t)(n0 + m)*512 + k0 + kk]);
            }
            #pragma unroll
            for (int t = 0; t < 8; t++) {
                int i = tid + 128*t; int n = i & 63, kk = i >> 6;
                cp4(&Bs[buf][(kk & 3)*PLB + n*4 + (kk >> 2)], &v[(size_t)(k0 + kk)*64 + n]);
            }
            cp_commit();
            cp_wait1();
        } else cp_wait0();
        __syncthreads();
        const float* a = As[it & 1];
        const float* bsm = Bs[it & 1];
        unsigned bu[4][4];
        #pragma unroll
        for (int j = 0; j < 4; j++) {
            float4 vv = *(const float4*)&bsm[c*PLB + (warp_n + j*8 + r)*4];
            bu[j][0]=f2t(vv.x); bu[j][1]=f2t(vv.y); bu[j][2]=f2t(vv.z); bu[j][3]=f2t(vv.w);
        }
        #pragma unroll
        for (int i = 0; i < 2; i++) {
            float4 lo = *(const float4*)&a[c*PLB + (warp_m + i*16 + r)*4];
            float4 hi = *(const float4*)&a[c*PLB + (warp_m + i*16 + r + 8)*4];
            unsigned a00=f2t(lo.x), a01=f2t(lo.y), a02=f2t(lo.z), a03=f2t(lo.w);
            unsigned a10=f2t(hi.x), a11=f2t(hi.y), a12=f2t(hi.z), a13=f2t(hi.w);
            #pragma unroll
            for (int j = 0; j < 4; j++) {
                mma8(acc[i][j], a00, a10, a01, a11, bu[j][0], bu[j][1]);
                mma8(acc[i][j], a02, a12, a03, a13, bu[j][2], bu[j][3]);
            }
        }
        __syncthreads();
    }
    #pragma unroll
    for (int j = 0; j < 4; j++) {
        int dk = warp_n + j*8 + 2*c;
        #pragma unroll
        for (int i = 0; i < 2; i++) {
            float4 d = acc[i][j];
            int R0 = n0 + warp_m + i*16 + r;
            *(float2*)&g_s1[((size_t)b*512 + R0)*768 + h*64 + dk] = make_float2(d.x, d.y);
            *(float2*)&g_s1[((size_t)b*512 + R0 + 8)*768 + h*64 + dk] = make_float2(d.z, d.w);
        }
    }
}

// ---------------- E accumulation: warp = n-row, lanes = e ------------------
__global__ void __launch_bounds__(256) e_kernel(const float* __restrict__ edge) {
    __shared__ float sP[32*68];   // [mm][np*8+h], stride 68 (float4-aligned)
    int tid = threadIdx.x;
    int np = tid >> 5, e = tid & 31;
    int b = blockIdx.y, n0 = blockIdx.x * 8;
    int n = n0 + np;
    const float* ep = edge + ((size_t)(b*512 + n) * 512) * 32 + e;
    float2 acc[4];
    #pragma unroll
    for (int j = 0; j < 4; j++) acc[j] = make_float2(0.f, 0.f);

    for (int c = 0; c < 16; c++) {
        __syncthreads();
        #pragma unroll
        for (int i = 0; i < 2; i++) {
            int idx = tid + 256*i;
            int rr = idx >> 3, seg = idx & 7;
            int hh = rr & 7, nn = rr >> 3;
            float4 v = *(const float4*)&g_p[(((size_t)(b*8 + hh)*512) + n0 + nn)*512 + c*32 + seg*4];
            sP[(seg*4+0)*68 + nn*8 + hh] = v.x;
            sP[(seg*4+1)*68 + nn*8 + hh] = v.y;
            sP[(seg*4+2)*68 + nn*8 + hh] = v.z;
            sP[(seg*4+3)*68 + nn*8 + hh] = v.w;
        }
        __syncthreads();
        #pragma unroll 4
        for (int mm = 0; mm < 32; mm++) {
            float ev = __ldg(ep + (size_t)(c*32 + mm) * 32);
            float2 ee = make_float2(ev, ev);
            float4 p0 = *(const float4*)&sP[mm*68 + np*8];
            float4 p1 = *(const float4*)&sP[mm*68 + np*8 + 4];
            ffma2(acc[0], make_float2(p0.x, p0.y), ee);
            ffma2(acc[1], make_float2(p0.z, p0.w), ee);
            ffma2(acc[2], make_float2(p1.x, p1.y), ee);
            ffma2(acc[3], make_float2(p1.z, p1.w), ee);
        }
    }
    float* o = &g_s1[((size_t)b*512 + n)*768 + 512];
    o[0*32 + e] = acc[0].x; o[1*32 + e] = acc[0].y;
    o[2*32 + e] = acc[1].x; o[3*32 + e] = acc[1].y;
    o[4*32 + e] = acc[2].x; o[5*32 + e] = acc[2].y;
    o[6*32 + e] = acc[3].x; o[7*32 + e] = acc[3].y;
}

// ---------------- final GEMM: tf32 MMA, CTA 64x64, 128 thr, grid (8,32) ----
__global__ void __launch_bounds__(128) final_kernel(float* __restrict__ out) {
    __shared__ float As[2][4*PLB];
    __shared__ float Bs[2][4*PLB];
    int m0 = blockIdx.y * 64, n0 = blockIdx.x * 64;
    int tid = threadIdx.x, lane = tid & 31, w = tid >> 5;
    int warp_m = (w & 1) * 32, warp_n = (w >> 1) * 32;
    int r = lane >> 2, c = lane & 3;

    float4 acc[2][4];
    #pragma unroll
    for (int i = 0; i < 2; i++)
        #pragma unroll
        for (int j = 0; j < 4; j++) acc[i][j] = make_float4(0.f,0.f,0.f,0.f);

    #pragma unroll
    for (int t = 0; t < 8; t++) {
        int i = tid + 128*t; int kk = i & 15, m = i >> 4;
        cp4(&As[0][(kk & 3)*PLB + m*4 + (kk >> 2)], &g_s1[(size_t)(m0 + m)*768 + kk]);
        cp4(&Bs[0][(kk & 3)*PLB + m*4 + (kk >> 2)], &g_wcomb[(size_t)(n0 + m)*768 + kk]);
    }
    cp_commit();

    for (int it = 0; it < 48; it++) {
        if (it < 47) {
            int k0 = (it + 1) * 16, buf = (it + 1) & 1;
            #pragma unroll
            for (int t = 0; t < 8; t++) {
                int i = tid + 128*t; int kk = i & 15, m = i >> 4;
                cp4(&As[buf][(kk & 3)*PLB + m*4 + (kk >> 2)], &g_s1[(size_t)(m0 + m)*768 + k0 + kk]);
                cp4(&Bs[buf][(kk & 3)*PLB + m*4 + (kk >> 2)], &g_wcomb[(size_t)(n0 + m)*768 + k0 + kk]);
            }
            cp_commit();
            cp_wait1();
        } else cp_wait0();
        __syncthreads();
        const float* a = As[it & 1];
        const float* bsm = Bs[it & 1];
        unsigned bu[4][4];
        #pragma unroll
        for (int j = 0; j < 4; j++) {
            float4 vv = *(const float4*)&bsm[c*PLB + (warp_n + j*8 + r)*4];
            bu[j][0]=f2t(vv.x); bu[j][1]=f2t(vv.y); bu[j][2]=f2t(vv.z); bu[j][3]=f2t(vv.w);
        }
        #pragma unroll
        for (int i = 0; i < 2; i++) {
            float4 lo = *(const float4*)&a[c*PLB + (warp_m + i*16 + r)*4];
            float4 hi = *(const float4*)&a[c*PLB + (warp_m + i*16 + r + 8)*4];
            unsigned a00=f2t(lo.x), a01=f2t(lo.y), a02=f2t(lo.z), a03=f2t(lo.w);
            unsigned a10=f2t(hi.x), a11=f2t(hi.y), a12=f2t(hi.z), a13=f2t(hi.w);
            #pragma unroll
            for (int j = 0; j < 4; j++) {
                mma8(acc[i][j], a00, a10, a01, a11, bu[j][0], bu[j][1]);
                mma8(acc[i][j], a02, a12, a03, a13, bu[j][2], bu[j][3]);
            }
        }
        __syncthreads();
    }
    #pragma unroll
    for (int j = 0; j < 4; j++) {
        int np0 = n0 + warp_n + j*8 + 2*c;
        float b0v = g_bfinal[np0], b1v = g_bfinal[np0 + 1];
        #pragma unroll
        for (int i = 0; i < 2; i++) {
            float4 d = acc[i][j];
            int R0 = m0 + warp_m + i*16 + r;
            *(float2*)&out[(size_t)R0*512 + np0] = make_float2(d.x + b0v, d.y + b1v);
            *(float2*)&out[(size_t)(R0 + 8)*512 + np0] = make_float2(d.z + b0v, d.w + b1v);
        }
    }
}

extern "C" void kernel_launch(void* const* d_in, const int* in_sizes, int n_in,
                              void* d_out, int out_size) {
    const float* Q    = (const float*)d_in[0];
    const float* K    = (const float*)d_in[1];
    const float* V    = (const float*)d_in[2];
    const unsigned char* mask = (const unsigned char*)d_in[3];
    const float* edge = (const float*)d_in[4];
    const float* W_Q  = (const float*)d_in[5];
    const float* b_Q  = (const float*)d_in[6];
    const float* W_K  = (const float*)d_in[7];
    const float* b_K  = (const float*)d_in[8];
    const float* W_V  = (const float*)d_in[9];
    const float* b_V  = (const float*)d_in[10];
    const float* W_Ke = (const float*)d_in[11];
    const float* b_Ke = (const float*)d_in[12];
    const float* W_eb = (const float*)d_in[13];
    const float* b_eb = (const float*)d_in[14];
    const float* W_eo = (const float*)d_in[15];
    const float* b_eo = (const float*)d_in[16];
    const float* W_o  = (const float*)d_in[17];
    const float* b_o  = (const float*)d_in[18];
    float* out = (float*)d_out;

    static cudaStream_t s1 = nullptr;
    static cudaEvent_t evF, evB, evS, evE;
    if (!s1) {
        cudaStreamCreateWithFlags(&s1, cudaStreamNonBlocking);
        cudaEventCreateWithFlags(&evF, cudaEventDisableTiming);
        cudaEventCreateWithFlags(&evB, cudaEventDisableTiming);
        cudaEventCreateWithFlags(&evS, cudaEventDisableTiming);
        cudaEventCreateWithFlags(&evE, cudaEventDisableTiming);
    }

    // fork: s1 = biask (needed by scores) then prep1/prep2 (needed by final)
    //       main = proj immediately
    cudaEventRecord(evF, 0);
    cudaStreamWaitEvent(s1, evF, 0);
    biask_kernel<<<2048, 256, 0, s1>>>(edge, mask, W_eb, b_eb);
    cudaEventRecord(evB, s1);
    prep1_kernel<<<512, 256, 0, s1>>>(W_Ke, b_Ke, W_eo, b_eo);
    prep2_kernel<<<512, 64, 0, s1>>>(W_o, b_o);

    proj_kernel<<<dim3(8, 32, 3), 128>>>(Q, K, V, W_Q, W_K, W_V, b_Q, b_K, b_V);
    cudaStreamWaitEvent(0, evB, 0);

    scores_kernel<<<dim3(16, 32), 256>>>();

    // fork: e (DRAM-bound) on s1 (after scores AND after prep, by stream order)
    cudaEventRecord(evS, 0);
    cudaStreamWaitEvent(s1, evS, 0);
    e_kernel<<<dim3(64, 4), 256, 0, s1>>>(edge);
    ctx_kernel<<<dim3(8, 32), 128>>>();
    cudaEventRecord(evE, s1);
    cudaStreamWaitEvent(0, evE, 0);

    final_kernel<<<dim3(8, 32), 128>>>(out);
}